// round 10
// baseline (speedup 1.0000x reference)
#include <cuda_runtime.h>
#include <cuda_fp16.h>
#include <cstdint>

#define NTOK 65536
#define D_IN 768
#define HID  512
#define CBD  256
#define CBK  512

// ---------------- scratch (device globals; no allocations) ----------------
__device__ __half g_xh[(size_t)NTOK * D_IN];
__device__ __half g_xl[(size_t)NTOK * D_IN];
__device__ __half g_hH[(size_t)NTOK * HID];
__device__ __half g_hL[(size_t)NTOK * HID];
__device__ __half g_zH[(size_t)NTOK * CBD];
__device__ __half g_zL[(size_t)NTOK * CBD];
__device__ float2 g_part[(size_t)NTOK * 8];   // per-64-code-block (val, idx)
__device__ __half g_W1TH[HID * D_IN];
__device__ __half g_W1TL[HID * D_IN];
__device__ __half g_W2TH[CBD * HID];
__device__ __half g_W2TL[CBD * HID];
__device__ __half g_cbH[CBK * CBD];
__device__ __half g_cbL[CBK * CBD];
__device__ float  g_T1[512 * 512];
__device__ float  g_R[512 * 768];
__device__ float  g_csq[CBK];
__device__ double g_commit;

// ---------------- helpers --------------------------------------------------
__device__ __forceinline__ void split_h(float v, __half& h, __half& l) {
    h = __float2half_rn(v);
    l = __float2half_rn(v - __half2float(h));
}
__device__ __forceinline__ void cp16(uint32_t saddr, const void* g) {
    asm volatile("cp.async.cg.shared.global [%0], [%1], 16;" :: "r"(saddr), "l"(g));
}
#define CP_COMMIT() asm volatile("cp.async.commit_group;" ::: "memory")
#define CP_WAIT2()  asm volatile("cp.async.wait_group 2;" ::: "memory")

#define LDSM4(r0, r1, r2, r3, addr) \
    asm volatile("ldmatrix.sync.aligned.m8n8.x4.shared.b16 {%0,%1,%2,%3}, [%4];" \
        : "=r"(r0), "=r"(r1), "=r"(r2), "=r"(r3) : "r"(addr))

#define MMA16(cc, aa, bb) \
    asm volatile("mma.sync.aligned.m16n8k16.row.col.f32.f16.f16.f32 " \
        "{%0,%1,%2,%3}, {%4,%5,%6,%7}, {%8,%9}, {%0,%1,%2,%3};" \
        : "+f"((cc)[0]), "+f"((cc)[1]), "+f"((cc)[2]), "+f"((cc)[3]) \
        : "r"((aa)[0]), "r"((aa)[1]), "r"((aa)[2]), "r"((aa)[3]), \
          "r"((bb)[0]), "r"((bb)[1]))

// =================== fp16 3x-split HMMA GEMM ===============================
// C[N, M] = op((Ah+Al)[N,K] @ (Bh+Bl)^T + bias); planes are __half [.,K] rowmaj.
// CTA tile 128x64, 4 warps each 64x32, K-tile 16, 4-stage cp.async pipeline.
// Stage (bytes): Ah@0 (128x48), Al@6144, Bh@12288 (64x48), Bl@15360.
// ARGMIN: per-row argmin of (csq[col] - 2*acc) over 64 cols -> part[token*8+bx].
#define STAGE_B  18432
#define HSMEM    (4 * STAGE_B)

template<bool RELU, bool HASBIAS, bool OSPLIT, bool ARGMIN>
__global__ void __launch_bounds__(128, 3) hmma_gemm(
    const __half* __restrict__ Ah, const __half* __restrict__ Al,
    const __half* __restrict__ Bh, const __half* __restrict__ Bl,
    const float* __restrict__ bias,
    float* __restrict__ C, __half* __restrict__ Ch, __half* __restrict__ Cl,
    float2* __restrict__ part, int K, int M)
{
    extern __shared__ char hsm[];
    __shared__ float2 red[2][64][2];
    uint32_t sbase;
    asm("{ .reg .u64 t; cvta.to.shared.u64 t, %1; cvt.u32.u64 %0, t; }"
        : "=r"(sbase) : "l"(hsm));

    const int tid  = threadIdx.x;
    const int lane = tid & 31;
    const int wid  = tid >> 5;
    const int wm   = wid & 1;           // row band (2 x 64)
    const int wn   = wid >> 1;          // col band (2 x 32)
    const int group = lane >> 2;
    const int tig   = lane & 3;
    const int brow = blockIdx.y << 7;   // 128 rows
    const int bcol = blockIdx.x << 6;   // 64 cols

    // loaders: A — thread owns one of 128 rows, both planes, both 16B chunks.
    //          B — threads 0-63 Bh row t, 64-127 Bl row t-64, both chunks.
    const __half* srcAh = Ah + (size_t)(brow + tid) * K;
    const __half* srcAl = Al + (size_t)(brow + tid) * K;
    const int blrow = tid & 63;
    const __half* srcB = ((tid >> 6) ? Bl : Bh) + (size_t)(bcol + blrow) * K;
    const uint32_t dA = sbase + (uint32_t)tid * 48;
    const uint32_t dB = sbase + 12288u + (uint32_t)(tid >> 6) * 3072 +
                        (uint32_t)blrow * 48;

    // ldmatrix lane offsets (bytes), 48B row stride
    const uint32_t aoff = (uint32_t)((lane & 15) * 48 + (lane >> 4) * 16);
    const uint32_t boff = (uint32_t)(((lane & 7) + ((lane >> 4) << 3)) * 48 +
                                     ((lane >> 3) & 1) * 16);

    float c[4][4][4];
#pragma unroll
    for (int i = 0; i < 4; i++)
#pragma unroll
        for (int j = 0; j < 4; j++)
#pragma unroll
            for (int k = 0; k < 4; k++) c[i][j][k] = 0.f;

    const int KT = K >> 4;
    auto issue = [&](int kt) {
        const uint32_t so = (uint32_t)(kt & 3) * STAGE_B;
        const size_t go = (size_t)kt << 4;
        cp16(dA + so,             srcAh + go);
        cp16(dA + so + 16,        srcAh + go + 8);
        cp16(dA + so + 6144,      srcAl + go);
        cp16(dA + so + 6144 + 16, srcAl + go + 8);
        cp16(dB + so,             srcB + go);
        cp16(dB + so + 16,        srcB + go + 8);
    };

    issue(0); CP_COMMIT();
    issue(1); CP_COMMIT();
    issue(2); CP_COMMIT();

    for (int kt = 0; kt < KT; kt++) {
        CP_WAIT2();
        __syncthreads();
        if (kt + 3 < KT) issue(kt + 3);
        CP_COMMIT();

        const uint32_t st = sbase + (uint32_t)(kt & 3) * STAGE_B;

        uint32_t bh[4][2], bl[4][2];
        {
            const uint32_t b0 = st + 12288 + (uint32_t)((wn << 5) * 48) + boff;
            LDSM4(bh[0][0], bh[0][1], bh[1][0], bh[1][1], b0);
            LDSM4(bh[2][0], bh[2][1], bh[3][0], bh[3][1], b0 + 768);
            LDSM4(bl[0][0], bl[0][1], bl[1][0], bl[1][1], b0 + 3072);
            LDSM4(bl[2][0], bl[2][1], bl[3][0], bl[3][1], b0 + 3072 + 768);
        }
#pragma unroll
        for (int mf = 0; mf < 4; mf++) {
            const uint32_t a0 = st + (uint32_t)(((wm << 6) + (mf << 4)) * 48) + aoff;
            uint32_t ah[4], al[4];
            LDSM4(ah[0], ah[1], ah[2], ah[3], a0);
            LDSM4(al[0], al[1], al[2], al[3], a0 + 6144);
#pragma unroll
            for (int nf = 0; nf < 4; nf++) MMA16(c[mf][nf], ah, bh[nf]);
#pragma unroll
            for (int nf = 0; nf < 4; nf++) MMA16(c[mf][nf], al, bh[nf]);
#pragma unroll
            for (int nf = 0; nf < 4; nf++) MMA16(c[mf][nf], ah, bl[nf]);
        }
    }

    if (ARGMIN) {
#pragma unroll
        for (int mf = 0; mf < 4; mf++) {
#pragma unroll
            for (int sub = 0; sub < 2; sub++) {
                float bv = 3.4e38f;
                int   bi = 0;
#pragma unroll
                for (int nf = 0; nf < 4; nf++) {
                    const int col = (wn << 5) + (nf << 3) + (tig << 1);
                    float d0 = g_csq[bcol + col]     - 2.f * c[mf][nf][sub * 2];
                    float d1 = g_csq[bcol + col + 1] - 2.f * c[mf][nf][sub * 2 + 1];
                    if (d0 < bv || (d0 == bv && col < bi))     { bv = d0; bi = col; }
                    if (d1 < bv || (d1 == bv && col + 1 < bi)) { bv = d1; bi = col + 1; }
                }
#pragma unroll
                for (int off = 1; off < 4; off <<= 1) {
                    float ov = __shfl_xor_sync(0xffffffffu, bv, off);
                    int   oi = __shfl_xor_sync(0xffffffffu, bi, off);
                    if (ov < bv || (ov == bv && oi < bi)) { bv = ov; bi = oi; }
                }
                if (tig == 0)
                    red[wm][(mf << 4) + group + sub * 8][wn] =
                        make_float2(bv, __int_as_float(bi));
            }
        }
        __syncthreads();
        {
            const int wmb = tid >> 6, rl = tid & 63;
            float bv = 3.4e38f;
            int   bi = 0;
#pragma unroll
            for (int w = 0; w < 2; w++) {
                float2 e = red[wmb][rl][w];
                int ei = __float_as_int(e.y);
                if (e.x < bv || (e.x == bv && ei < bi)) { bv = e.x; bi = ei; }
            }
            const int token = brow + (wmb << 6) + rl;
            part[(size_t)token * 8 + blockIdx.x] = make_float2(bv, (float)(bcol + bi));
        }
        return;
    }

    // normal epilogue
#pragma unroll
    for (int mf = 0; mf < 4; mf++) {
#pragma unroll
        for (int nf = 0; nf < 4; nf++) {
            const int row = brow + (wm << 6) + (mf << 4) + group;
            const int col = bcol + (wn << 5) + (nf << 3) + (tig << 1);
            float bx = 0.f, by = 0.f;
            if (HASBIAS) { bx = __ldg(bias + col); by = __ldg(bias + col + 1); }
            float2 o0, o1;
            o0.x = c[mf][nf][0] + bx;  o0.y = c[mf][nf][1] + by;
            o1.x = c[mf][nf][2] + bx;  o1.y = c[mf][nf][3] + by;
            if (RELU) {
                o0.x = fmaxf(o0.x, 0.f); o0.y = fmaxf(o0.y, 0.f);
                o1.x = fmaxf(o1.x, 0.f); o1.y = fmaxf(o1.y, 0.f);
            }
            if (OSPLIT) {
                __half hx, lx, hy, ly;
                split_h(o0.x, hx, lx); split_h(o0.y, hy, ly);
                *(__half2*)(Ch + (size_t)row * M + col) = __halves2half2(hx, hy);
                *(__half2*)(Cl + (size_t)row * M + col) = __halves2half2(lx, ly);
                split_h(o1.x, hx, lx); split_h(o1.y, hy, ly);
                *(__half2*)(Ch + (size_t)(row + 8) * M + col) = __halves2half2(hx, hy);
                *(__half2*)(Cl + (size_t)(row + 8) * M + col) = __halves2half2(lx, ly);
            } else {
                *(float2*)(C + (size_t)row * M + col)       = o0;
                *(float2*)(C + (size_t)(row + 8) * M + col) = o1;
            }
        }
    }
}

// ---------------- prep: cb split + csq + commit=0 --------------------------
__global__ void prep_kernel(const float* __restrict__ cb) {
    const int b = blockIdx.x;
    const int t = threadIdx.x;
    if (b < 512) {
        int idx = b * 256 + t;
        __half h, l;
        split_h(cb[idx], h, l);
        g_cbH[idx] = h;
        g_cbL[idx] = l;
    } else {
        int k = (b - 512) * 256 + t;
        if (b == 512 && t == 0) g_commit = 0.0;
        const float* row = cb + (size_t)k * CBD;
        float s = 0.f;
#pragma unroll 8
        for (int c = 0; c < CBD; c += 4) {
            float4 v = *(const float4*)(row + c);
            s += v.x*v.x + v.y*v.y + v.z*v.z + v.w*v.w;
        }
        g_csq[k] = s;
    }
}

// ---------------- split x into fp16 hi/lo planes ---------------------------
__global__ void split_x_kernel(const float* __restrict__ x) {
    size_t i = ((size_t)blockIdx.x * 256 + threadIdx.x) * 4;
    float4 v = *(const float4*)(x + i);
    __half h0, l0, h1, l1, h2, l2, h3, l3;
    split_h(v.x, h0, l0); split_h(v.y, h1, l1);
    split_h(v.z, h2, l2); split_h(v.w, h3, l3);
    *(__half2*)(g_xh + i)     = __halves2half2(h0, h1);
    *(__half2*)(g_xh + i + 2) = __halves2half2(h2, h3);
    *(__half2*)(g_xl + i)     = __halves2half2(l0, l1);
    *(__half2*)(g_xl + i + 2) = __halves2half2(l2, l3);
}

// ---------------- transpose + split: W[K,M] -> half planes [M,K] -----------
__global__ void transpose_split(const float* __restrict__ W,
                                __half* __restrict__ WTh, __half* __restrict__ WTl,
                                int K, int M) {
    int idx = blockIdx.x * 256 + threadIdx.x;
    if (idx < K * M) {
        int m = idx / K, k = idx - m * K;
        __half h, l;
        split_h(W[(size_t)k * M + m], h, l);
        WTh[idx] = h;
        WTl[idx] = l;
    }
}

// -------- fp32 SGEMM 64x64 tiles for the tiny decoder-table GEMMs ---------
template<bool RELU, bool HASBIAS>
__global__ void __launch_bounds__(256) sgemm64(
    const float* __restrict__ A, const float* __restrict__ B,
    const float* __restrict__ bias, float* __restrict__ C,
    int N, int K, int M)
{
    __shared__ float As[16][68];
    __shared__ float Bs[16][68];
    const int tid  = threadIdx.x;
    const int tx   = tid & 15;
    const int ty   = tid >> 4;
    const int brow = blockIdx.y << 6;
    const int bcol = blockIdx.x << 6;

    const int ar = tid >> 2;
    const int ac = (tid & 3) << 2;
    const float* aptr = A + (size_t)(brow + ar) * K + ac;
    const int br = tid >> 4;
    const int bc = (tid & 15) << 2;
    const float* bptr = B + (size_t)br * M + bcol + bc;

    float acc[4][4];
#pragma unroll
    for (int i = 0; i < 4; i++)
#pragma unroll
        for (int j = 0; j < 4; j++) acc[i][j] = 0.f;

    for (int k0 = 0; k0 < K; k0 += 16) {
        float4 av = *(const float4*)(aptr + k0);
        float4 bv = *(const float4*)(bptr + (size_t)k0 * M);
        As[ac + 0][ar] = av.x;  As[ac + 1][ar] = av.y;
        As[ac + 2][ar] = av.z;  As[ac + 3][ar] = av.w;
        *(float4*)&Bs[br][bc] = bv;
        __syncthreads();
#pragma unroll
        for (int kk = 0; kk < 16; kk++) {
            float4 a4 = *(const float4*)&As[kk][ty << 2];
            float4 b4 = *(const float4*)&Bs[kk][tx << 2];
            float arr[4] = {a4.x, a4.y, a4.z, a4.w};
            float brr[4] = {b4.x, b4.y, b4.z, b4.w};
#pragma unroll
            for (int i = 0; i < 4; i++)
#pragma unroll
                for (int j = 0; j < 4; j++)
                    acc[i][j] = fmaf(arr[i], brr[j], acc[i][j]);
        }
        __syncthreads();
    }

    float4 bb = make_float4(0.f, 0.f, 0.f, 0.f);
    if (HASBIAS) bb = *(const float4*)(bias + bcol + (tx << 2));
#pragma unroll
    for (int i = 0; i < 4; i++) {
        float4 o;
        o.x = acc[i][0] + bb.x;
        o.y = acc[i][1] + bb.y;
        o.z = acc[i][2] + bb.z;
        o.w = acc[i][3] + bb.w;
        if (RELU) {
            o.x = fmaxf(o.x, 0.f); o.y = fmaxf(o.y, 0.f);
            o.z = fmaxf(o.z, 0.f); o.w = fmaxf(o.w, 0.f);
        }
        *(float4*)(C + (size_t)(brow + (ty << 2) + i) * M + bcol + (tx << 2)) = o;
    }
}

// ---- VQ: reduce 8 partials + commit partial + recon gather ---------------
__global__ void __launch_bounds__(256) vq_recon_kernel(
    const float2* __restrict__ part,
    const __half* __restrict__ zH, const __half* __restrict__ zL,
    const float* __restrict__ R, float* __restrict__ out_idx,
    float* __restrict__ out_recon)
{
    __shared__ float s_part[8];
    const int tid = threadIdx.x;
    const int token = (blockIdx.x << 5) + (tid >> 3);
    const int lp = tid & 7;

    float2 e = part[(size_t)token * 8 + lp];
    float best = e.x;
    int   bidx = (int)e.y;
#pragma unroll
    for (int off = 1; off < 8; off <<= 1) {
        float ob = __shfl_xor_sync(0xffffffffu, best, off);
        int   oi = __shfl_xor_sync(0xffffffffu, bidx, off);
        if (ob < best || (ob == best && oi < bidx)) { best = ob; bidx = oi; }
    }

    // ||z||^2 from half planes (z = zH + zL); 32 coords per lane
    const __half2* zh2 = (const __half2*)(zH + (size_t)token * CBD + (lp << 5));
    const __half2* zl2 = (const __half2*)(zL + (size_t)token * CBD + (lp << 5));
    float s = 0.f;
#pragma unroll
    for (int i = 0; i < 16; i++) {
        float2 a = __half22float2(zh2[i]);
        float2 b = __half22float2(zl2[i]);
        float vx = a.x + b.x, vy = a.y + b.y;
        s += vx * vx + vy * vy;
    }
    s += __shfl_xor_sync(0xffffffffu, s, 1);
    s += __shfl_xor_sync(0xffffffffu, s, 2);
    s += __shfl_xor_sync(0xffffffffu, s, 4);

    float cv = (lp == 0) ? (s + best) : 0.f;
    if (lp == 0) out_idx[token] = (float)bidx;

    const float4* src = (const float4*)(R + (size_t)bidx * D_IN + lp * 96);
    float4*       dst = (float4*)(out_recon + (size_t)token * D_IN + lp * 96);
#pragma unroll 4
    for (int i = 0; i < 24; i++) dst[i] = src[i];

#pragma unroll
    for (int off = 16; off; off >>= 1) cv += __shfl_xor_sync(0xffffffffu, cv, off);
    if ((tid & 31) == 0) s_part[tid >> 5] = cv;
    __syncthreads();
    if (tid == 0) {
        float t = 0.f;
#pragma unroll
        for (int w = 0; w < 8; w++) t += s_part[w];
        atomicAdd(&g_commit, (double)t);
    }
}

__global__ void finalize_kernel(float* __restrict__ out_loss) {
    *out_loss = (float)(g_commit * (1.0 / ((double)NTOK * CBD)));
}

// ---------------- launch ---------------------------------------------------
extern "C" void kernel_launch(void* const* d_in, const int* in_sizes, int n_in,
                              void* d_out, int out_size) {
    const float* x  = (const float*)d_in[0];
    const float* W1 = (const float*)d_in[1];
    const float* b1 = (const float*)d_in[2];
    const float* W2 = (const float*)d_in[3];
    const float* b2 = (const float*)d_in[4];
    const float* cb = (const float*)d_in[5];
    const float* W3 = (const float*)d_in[6];
    const float* b3 = (const float*)d_in[7];
    const float* W4 = (const float*)d_in[8];
    const float* b4 = (const float*)d_in[9];

    float* out       = (float*)d_out;
    float* out_recon = out;
    float* out_idx   = out + (size_t)NTOK * D_IN;
    float* out_loss  = out_idx + NTOK;

    __half *pxh, *pxl, *phH, *phL, *pzH, *pzL;
    __half *pW1TH, *pW1TL, *pW2TH, *pW2TL, *pcbH, *pcbL;
    float *pT1, *pR;
    float2* ppart;
    cudaGetSymbolAddress((void**)&pxh,   g_xh);
    cudaGetSymbolAddress((void**)&pxl,   g_xl);
    cudaGetSymbolAddress((void**)&phH,   g_hH);
    cudaGetSymbolAddress((void**)&phL,   g_hL);
    cudaGetSymbolAddress((void**)&pzH,   g_zH);
    cudaGetSymbolAddress((void**)&pzL,   g_zL);
    cudaGetSymbolAddress((void**)&ppart, g_part);
    cudaGetSymbolAddress((void**)&pT1,   g_T1);
    cudaGetSymbolAddress((void**)&pR,    g_R);
    cudaGetSymbolAddress((void**)&pW1TH, g_W1TH);
    cudaGetSymbolAddress((void**)&pW1TL, g_W1TL);
    cudaGetSymbolAddress((void**)&pW2TH, g_W2TH);
    cudaGetSymbolAddress((void**)&pW2TL, g_W2TL);
    cudaGetSymbolAddress((void**)&pcbH,  g_cbH);
    cudaGetSymbolAddress((void**)&pcbL,  g_cbL);

    static bool attr_done = false;
    if (!attr_done) {
        cudaFuncSetAttribute(hmma_gemm<true,  true,  true,  false>,
                             cudaFuncAttributeMaxDynamicSharedMemorySize, HSMEM);
        cudaFuncSetAttribute(hmma_gemm<false, true,  true,  false>,
                             cudaFuncAttributeMaxDynamicSharedMemorySize, HSMEM);
        cudaFuncSetAttribute(hmma_gemm<false, false, false, true >,
                             cudaFuncAttributeMaxDynamicSharedMemorySize, HSMEM);
        attr_done = true;
    }

    // [0] prep: cb split + csq + commit=0
    prep_kernel<<<514, 256>>>(cb);
    // [1] split x into fp16 planes
    split_x_kernel<<<(NTOK * D_IN / 4) / 256, 256>>>(x);
    // [2] W1 transpose+split
    transpose_split<<<(HID * D_IN + 255) / 256, 256>>>(W1, pW1TH, pW1TL, D_IN, HID);
    // [3] h = relu(x @ W1 + b1), split output   (ncu-captured slot)
    hmma_gemm<true,  true,  true,  false><<<dim3(HID / 64, NTOK / 128), 128, HSMEM>>>(
        pxh, pxl, pW1TH, pW1TL, b1, nullptr, phH, phL, nullptr, D_IN, HID);
    // [4] W2 transpose+split
    transpose_split<<<(CBD * HID + 255) / 256, 256>>>(W2, pW2TH, pW2TL, HID, CBD);
    // [5][6] decoder table (tiny, fp32, 64x64 tiles)
    sgemm64<true , true ><<<dim3(HID  / 64, 512 / 64), 256>>>(cb,  W3, b3, pT1, 512, CBD, HID);
    sgemm64<false, true ><<<dim3(D_IN / 64, 512 / 64), 256>>>(pT1, W4, b4, pR,  512, HID, D_IN);
    // [7] z = h @ W2 + b2, split output
    hmma_gemm<false, true,  true,  false><<<dim3(CBD / 64, NTOK / 128), 128, HSMEM>>>(
        phH, phL, pW2TH, pW2TL, b2, nullptr, pzH, pzL, nullptr, HID, CBD);
    // [8] dots + fused argmin -> partials (8 per token)
    hmma_gemm<false, false, false, true ><<<dim3(CBK / 64, NTOK / 128), 128, HSMEM>>>(
        pzH, pzL, pcbH, pcbL, nullptr, nullptr, nullptr, nullptr, ppart, CBD, CBK);
    // [9] reduce partials + commit + recon gather
    vq_recon_kernel<<<NTOK / 32, 256>>>(ppart, pzH, pzL, pR, out_idx, out_recon);
    // [10] loss
    finalize_kernel<<<1, 1>>>(out_loss);
}

// round 12
// speedup vs baseline: 1.3519x; 1.3519x over previous
#include <cuda_runtime.h>
#include <cuda_fp16.h>
#include <cstdint>

#define NTOK 65536
#define D_IN 768
#define HID  512
#define CBD  256
#define CBK  512

// ---------------- scratch (device globals; no allocations) ----------------
__device__ __half g_hH[(size_t)NTOK * HID];
__device__ __half g_hL[(size_t)NTOK * HID];
__device__ __half g_zH[(size_t)NTOK * CBD];
__device__ __half g_zL[(size_t)NTOK * CBD];
__device__ float2 g_part[(size_t)NTOK * 4];   // per-128-code-block (val, idx)
__device__ __half g_W1TH[HID * D_IN];
__device__ __half g_W1TL[HID * D_IN];
__device__ __half g_W2TH[CBD * HID];
__device__ __half g_W2TL[CBD * HID];
__device__ __half g_cbH[CBK * CBD];
__device__ __half g_cbL[CBK * CBD];
__device__ float  g_T1[512 * 512];
__device__ float  g_R[512 * 768];
__device__ float  g_csq[CBK];
__device__ double g_commit;

// ---------------- helpers --------------------------------------------------
__device__ __forceinline__ void split_h(float v, __half& h, __half& l) {
    h = __float2half_rn(v);
    l = __float2half_rn(v - __half2float(h));
}
__device__ __forceinline__ void cp16(uint32_t saddr, const void* g) {
    asm volatile("cp.async.cg.shared.global [%0], [%1], 16;" :: "r"(saddr), "l"(g));
}
#define CP_COMMIT() asm volatile("cp.async.commit_group;" ::: "memory")
#define CP_WAIT2()  asm volatile("cp.async.wait_group 2;" ::: "memory")

#define LDSM4(r0, r1, r2, r3, addr) \
    asm volatile("ldmatrix.sync.aligned.m8n8.x4.shared.b16 {%0,%1,%2,%3}, [%4];" \
        : "=r"(r0), "=r"(r1), "=r"(r2), "=r"(r3) : "r"(addr))

#define MMA16(cc, aa, bb) \
    asm volatile("mma.sync.aligned.m16n8k16.row.col.f32.f16.f16.f32 " \
        "{%0,%1,%2,%3}, {%4,%5,%6,%7}, {%8,%9}, {%0,%1,%2,%3};" \
        : "+f"((cc)[0]), "+f"((cc)[1]), "+f"((cc)[2]), "+f"((cc)[3]) \
        : "r"((aa)[0]), "r"((aa)[1]), "r"((aa)[2]), "r"((aa)[3]), \
          "r"((bb)[0]), "r"((bb)[1]))

// =================== fp16 3x-split HMMA GEMM ===============================
// C[N, M] = op((Ah+Al)[N,K] @ (Bh+Bl)^T + bias); planes are __half [.,K] rowmaj.
// CTA tile 128x128, 8 warps each 64x32, K-tile 16, 4-stage pipeline.
// Stage (bytes): Ah@0, Al@6144, Bh@12288, Bl@18432; row stride 48B (24 halves).
// ACONV: A is fp32 (Af); loaded via register prefetch, split + STS in-kernel.
// ARGMIN: no C store; per-row argmin of (csq[col] - 2*acc) over the 128 cols.
#define STAGE_B  24576
#define HSMEM    (4 * STAGE_B)

template<bool RELU, bool HASBIAS, bool OSPLIT, bool ARGMIN, bool ACONV>
__global__ void __launch_bounds__(256, 2) hmma_gemm(
    const float* __restrict__ Af,
    const __half* __restrict__ Ah, const __half* __restrict__ Al,
    const __half* __restrict__ Bh, const __half* __restrict__ Bl,
    const float* __restrict__ bias,
    float* __restrict__ C, __half* __restrict__ Ch, __half* __restrict__ Cl,
    float2* __restrict__ part, int K, int M)
{
    extern __shared__ char hsm[];
    __shared__ float2 red[2][64][4];
    uint32_t sbase;
    asm("{ .reg .u64 t; cvta.to.shared.u64 t, %1; cvt.u32.u64 %0, t; }"
        : "=r"(sbase) : "l"(hsm));

    const int tid  = threadIdx.x;
    const int lane = tid & 31;
    const int wid  = tid >> 5;
    const int wm   = wid & 1;
    const int wn   = wid >> 1;
    const int group = lane >> 2;
    const int tig   = lane & 3;
    const int brow = blockIdx.y << 7;
    const int bcol = blockIdx.x << 7;

    // loader: thread -> (row, 16B chunk)
    const int lrow = tid >> 1;
    const int lchk = tid & 1;
    const uint32_t soff = sbase + (uint32_t)(lrow * 48 + lchk * 16);
    const uint32_t doff = (uint32_t)(lrow * 48 + lchk * 16);   // byte off in stage
    const __half* gAh = ACONV ? nullptr : (Ah + (size_t)(brow + lrow) * K + lchk * 8);
    const __half* gAl = ACONV ? nullptr : (Al + (size_t)(brow + lrow) * K + lchk * 8);
    const float*  gAf = ACONV ? (Af + (size_t)(brow + lrow) * K + lchk * 8) : nullptr;
    const __half* gBh = Bh + (size_t)(bcol + lrow) * K + lchk * 8;
    const __half* gBl = Bl + (size_t)(bcol + lrow) * K + lchk * 8;

    // ldmatrix lane offsets (bytes)
    const uint32_t aoff = (uint32_t)(((lane & 15) * 24 + (lane >> 4) * 8) * 2);
    const uint32_t boff = (uint32_t)((((lane & 7) + ((lane >> 4) << 3)) * 24 +
                                      ((lane >> 3) & 1) * 8) * 2);

    float c[4][4][4];
#pragma unroll
    for (int i = 0; i < 4; i++)
#pragma unroll
        for (int j = 0; j < 4; j++)
#pragma unroll
            for (int k = 0; k < 4; k++) c[i][j][k] = 0.f;

    const int KT = K >> 4;
    auto issue = [&](int kt) {
        const uint32_t sb = soff + (uint32_t)(kt & 3) * STAGE_B;
        const size_t go = (size_t)kt << 4;
        cp16(sb + 12288, gBh + go);
        cp16(sb + 18432, gBl + go);
        if (!ACONV) {
            cp16(sb,        gAh + go);
            cp16(sb + 6144, gAl + go);
        }
    };

    float4 va0, va1;
    if (ACONV) { va0 = *(const float4*)gAf; va1 = *(const float4*)(gAf + 4); }
    issue(0); CP_COMMIT();
    issue(1); CP_COMMIT();
    issue(2); CP_COMMIT();

    for (int kt = 0; kt < KT; kt++) {
        if (ACONV) {
            // split + STS A(kt), then prefetch A(kt+1)
            __half2 H2[4], L2[4];
            {
                __half h0, l0, h1, l1;
                split_h(va0.x, h0, l0); split_h(va0.y, h1, l1);
                H2[0] = __halves2half2(h0, h1); L2[0] = __halves2half2(l0, l1);
                split_h(va0.z, h0, l0); split_h(va0.w, h1, l1);
                H2[1] = __halves2half2(h0, h1); L2[1] = __halves2half2(l0, l1);
                split_h(va1.x, h0, l0); split_h(va1.y, h1, l1);
                H2[2] = __halves2half2(h0, h1); L2[2] = __halves2half2(l0, l1);
                split_h(va1.z, h0, l0); split_h(va1.w, h1, l1);
                H2[3] = __halves2half2(h0, h1); L2[3] = __halves2half2(l0, l1);
            }
            char* stp = hsm + (size_t)(kt & 3) * STAGE_B + doff;
            *(uint4*)stp          = *(const uint4*)H2;
            *(uint4*)(stp + 6144) = *(const uint4*)L2;
            if (kt + 1 < KT) {
                const float* p = gAf + (size_t)(kt + 1) * 16;
                va0 = *(const float4*)p;
                va1 = *(const float4*)(p + 4);
            }
        }
        CP_WAIT2();
        __syncthreads();
        if (kt + 3 < KT) issue(kt + 3);
        CP_COMMIT();

        const uint32_t st = sbase + (uint32_t)(kt & 3) * STAGE_B;

        uint32_t bh[4][2], bl[4][2];
        {
            const uint32_t b0 = st + 12288 + (uint32_t)((wn << 5) * 48) + boff;
            const uint32_t b1 = b0 + 16 * 48;
            LDSM4(bh[0][0], bh[0][1], bh[1][0], bh[1][1], b0);
            LDSM4(bh[2][0], bh[2][1], bh[3][0], bh[3][1], b1);
            LDSM4(bl[0][0], bl[0][1], bl[1][0], bl[1][1], b0 + 6144);
            LDSM4(bl[2][0], bl[2][1], bl[3][0], bl[3][1], b1 + 6144);
        }
#pragma unroll
        for (int mf = 0; mf < 4; mf++) {
            const uint32_t a0 = st + (uint32_t)(((wm << 6) + (mf << 4)) * 48) + aoff;
            uint32_t ah[4], al[4];
            LDSM4(ah[0], ah[1], ah[2], ah[3], a0);
            LDSM4(al[0], al[1], al[2], al[3], a0 + 6144);
#pragma unroll
            for (int nf = 0; nf < 4; nf++) MMA16(c[mf][nf], ah, bh[nf]);
#pragma unroll
            for (int nf = 0; nf < 4; nf++) MMA16(c[mf][nf], al, bh[nf]);
#pragma unroll
            for (int nf = 0; nf < 4; nf++) MMA16(c[mf][nf], ah, bl[nf]);
        }
    }

    if (ARGMIN) {
#pragma unroll
        for (int mf = 0; mf < 4; mf++) {
#pragma unroll
            for (int sub = 0; sub < 2; sub++) {
                float bv = 3.4e38f;
                int   bi = 0;
#pragma unroll
                for (int nf = 0; nf < 4; nf++) {
                    const int col = (wn << 5) + (nf << 3) + (tig << 1);
                    float d0 = __ldg(&g_csq[bcol + col])     - 2.f * c[mf][nf][sub * 2];
                    float d1 = __ldg(&g_csq[bcol + col + 1]) - 2.f * c[mf][nf][sub * 2 + 1];
                    if (d0 < bv || (d0 == bv && col < bi))     { bv = d0; bi = col; }
                    if (d1 < bv || (d1 == bv && col + 1 < bi)) { bv = d1; bi = col + 1; }
                }
#pragma unroll
                for (int off = 1; off < 4; off <<= 1) {
                    float ov = __shfl_xor_sync(0xffffffffu, bv, off);
                    int   oi = __shfl_xor_sync(0xffffffffu, bi, off);
                    if (ov < bv || (ov == bv && oi < bi)) { bv = ov; bi = oi; }
                }
                if (tig == 0)
                    red[wm][(mf << 4) + group + sub * 8][wn] =
                        make_float2(bv, __int_as_float(bi));
            }
        }
        __syncthreads();
        if (tid < 128) {
            const int wmb = tid >> 6, rl = tid & 63;
            float bv = 3.4e38f;
            int   bi = 0;
#pragma unroll
            for (int w = 0; w < 4; w++) {
                float2 e = red[wmb][rl][w];
                int ei = __float_as_int(e.y);
                if (e.x < bv || (e.x == bv && ei < bi)) { bv = e.x; bi = ei; }
            }
            const int token = brow + (wmb << 6) + rl;
            part[(size_t)token * 4 + blockIdx.x] = make_float2(bv, (float)(bcol + bi));
        }
        return;
    }

    // normal epilogue
#pragma unroll
    for (int mf = 0; mf < 4; mf++) {
#pragma unroll
        for (int nf = 0; nf < 4; nf++) {
            const int row = brow + (wm << 6) + (mf << 4) + group;
            const int col = bcol + (wn << 5) + (nf << 3) + (tig << 1);
            float bx = 0.f, by = 0.f;
            if (HASBIAS) { bx = __ldg(bias + col); by = __ldg(bias + col + 1); }
            float2 o0, o1;
            o0.x = c[mf][nf][0] + bx;  o0.y = c[mf][nf][1] + by;
            o1.x = c[mf][nf][2] + bx;  o1.y = c[mf][nf][3] + by;
            if (RELU) {
                o0.x = fmaxf(o0.x, 0.f); o0.y = fmaxf(o0.y, 0.f);
                o1.x = fmaxf(o1.x, 0.f); o1.y = fmaxf(o1.y, 0.f);
            }
            if (OSPLIT) {
                __half hx, lx, hy, ly;
                split_h(o0.x, hx, lx); split_h(o0.y, hy, ly);
                *(__half2*)(Ch + (size_t)row * M + col) = __halves2half2(hx, hy);
                *(__half2*)(Cl + (size_t)row * M + col) = __halves2half2(lx, ly);
                split_h(o1.x, hx, lx); split_h(o1.y, hy, ly);
                *(__half2*)(Ch + (size_t)(row + 8) * M + col) = __halves2half2(hx, hy);
                *(__half2*)(Cl + (size_t)(row + 8) * M + col) = __halves2half2(lx, ly);
            } else {
                *(float2*)(C + (size_t)row * M + col)       = o0;
                *(float2*)(C + (size_t)(row + 8) * M + col) = o1;
            }
        }
    }
}

// ---------------- prep: cb split + csq + commit=0 --------------------------
__global__ void prep_kernel(const float* __restrict__ cb) {
    const int b = blockIdx.x;
    const int t = threadIdx.x;
    if (b < 512) {
        int idx = b * 256 + t;
        __half h, l;
        split_h(cb[idx], h, l);
        g_cbH[idx] = h;
        g_cbL[idx] = l;
    } else {
        int k = (b - 512) * 256 + t;
        if (b == 512 && t == 0) g_commit = 0.0;
        const float* row = cb + (size_t)k * CBD;
        float s = 0.f;
#pragma unroll 8
        for (int c = 0; c < CBD; c += 4) {
            float4 v = *(const float4*)(row + c);
            s += v.x*v.x + v.y*v.y + v.z*v.z + v.w*v.w;
        }
        g_csq[k] = s;
    }
}

// ---------------- transpose + split: W[K,M] -> half planes [M,K] -----------
__global__ void transpose_split(const float* __restrict__ W,
                                __half* __restrict__ WTh, __half* __restrict__ WTl,
                                int K, int M) {
    int idx = blockIdx.x * 256 + threadIdx.x;
    if (idx < K * M) {
        int m = idx / K, k = idx - m * K;
        __half h, l;
        split_h(W[(size_t)k * M + m], h, l);
        WTh[idx] = h;
        WTl[idx] = l;
    }
}

// -------- fp32 SGEMM 64x64 tiles for the tiny decoder-table GEMMs ---------
template<bool RELU, bool HASBIAS>
__global__ void __launch_bounds__(256) sgemm64(
    const float* __restrict__ A, const float* __restrict__ B,
    const float* __restrict__ bias, float* __restrict__ C,
    int N, int K, int M)
{
    __shared__ float As[16][68];
    __shared__ float Bs[16][68];
    const int tid  = threadIdx.x;
    const int tx   = tid & 15;
    const int ty   = tid >> 4;
    const int brow = blockIdx.y << 6;
    const int bcol = blockIdx.x << 6;

    const int ar = tid >> 2;
    const int ac = (tid & 3) << 2;
    const float* aptr = A + (size_t)(brow + ar) * K + ac;
    const int br = tid >> 4;
    const int bc = (tid & 15) << 2;
    const float* bptr = B + (size_t)br * M + bcol + bc;

    float acc[4][4];
#pragma unroll
    for (int i = 0; i < 4; i++)
#pragma unroll
        for (int j = 0; j < 4; j++) acc[i][j] = 0.f;

    for (int k0 = 0; k0 < K; k0 += 16) {
        float4 av = *(const float4*)(aptr + k0);
        float4 bv = *(const float4*)(bptr + (size_t)k0 * M);
        As[ac + 0][ar] = av.x;  As[ac + 1][ar] = av.y;
        As[ac + 2][ar] = av.z;  As[ac + 3][ar] = av.w;
        *(float4*)&Bs[br][bc] = bv;
        __syncthreads();
#pragma unroll
        for (int kk = 0; kk < 16; kk++) {
            float4 a4 = *(const float4*)&As[kk][ty << 2];
            float4 b4 = *(const float4*)&Bs[kk][tx << 2];
            float arr[4] = {a4.x, a4.y, a4.z, a4.w};
            float brr[4] = {b4.x, b4.y, b4.z, b4.w};
#pragma unroll
            for (int i = 0; i < 4; i++)
#pragma unroll
                for (int j = 0; j < 4; j++)
                    acc[i][j] = fmaf(arr[i], brr[j], acc[i][j]);
        }
        __syncthreads();
    }

    float4 bb = make_float4(0.f, 0.f, 0.f, 0.f);
    if (HASBIAS) bb = *(const float4*)(bias + bcol + (tx << 2));
#pragma unroll
    for (int i = 0; i < 4; i++) {
        float4 o;
        o.x = acc[i][0] + bb.x;
        o.y = acc[i][1] + bb.y;
        o.z = acc[i][2] + bb.z;
        o.w = acc[i][3] + bb.w;
        if (RELU) {
            o.x = fmaxf(o.x, 0.f); o.y = fmaxf(o.y, 0.f);
            o.z = fmaxf(o.z, 0.f); o.w = fmaxf(o.w, 0.f);
        }
        *(float4*)(C + (size_t)(brow + (ty << 2) + i) * M + bcol + (tx << 2)) = o;
    }
}

// ---- VQ: reduce 4 partials + commit partial + recon gather ---------------
__global__ void __launch_bounds__(256) vq_recon_kernel(
    const float2* __restrict__ part,
    const __half* __restrict__ zH, const __half* __restrict__ zL,
    const float* __restrict__ R, float* __restrict__ out_idx,
    float* __restrict__ out_recon)
{
    __shared__ float s_part[8];
    const int tid = threadIdx.x;
    const int token = (blockIdx.x << 6) + (tid >> 2);
    const int lpart = tid & 3;

    float2 e = part[(size_t)token * 4 + lpart];
    float best = e.x;
    int   bidx = (int)e.y;
#pragma unroll
    for (int off = 1; off < 4; off <<= 1) {
        float ob = __shfl_xor_sync(0xffffffffu, best, off);
        int   oi = __shfl_xor_sync(0xffffffffu, bidx, off);
        if (ob < best || (ob == best && oi < bidx)) { best = ob; bidx = oi; }
    }

    // ||z||^2 from half planes (z = zH + zL); 64 coords per lane
    const __half2* zh2 = (const __half2*)(zH + (size_t)token * CBD + (lpart << 6));
    const __half2* zl2 = (const __half2*)(zL + (size_t)token * CBD + (lpart << 6));
    float s = 0.f;
#pragma unroll
    for (int i = 0; i < 32; i++) {
        float2 a = __half22float2(zh2[i]);
        float2 b = __half22float2(zl2[i]);
        float vx = a.x + b.x, vy = a.y + b.y;
        s += vx * vx + vy * vy;
    }
    s += __shfl_xor_sync(0xffffffffu, s, 1);
    s += __shfl_xor_sync(0xffffffffu, s, 2);

    float cv = (lpart == 0) ? (s + best) : 0.f;
    if (lpart == 0) out_idx[token] = (float)bidx;

    const float4* src = (const float4*)(R + (size_t)bidx * D_IN + lpart * 192);
    float4*       dst = (float4*)(out_recon + (size_t)token * D_IN + lpart * 192);
#pragma unroll 4
    for (int i = 0; i < 48; i++) dst[i] = src[i];

#pragma unroll
    for (int off = 16; off; off >>= 1) cv += __shfl_xor_sync(0xffffffffu, cv, off);
    if ((tid & 31) == 0) s_part[tid >> 5] = cv;
    __syncthreads();
    if (tid == 0) {
        float t = 0.f;
#pragma unroll
        for (int w = 0; w < 8; w++) t += s_part[w];
        atomicAdd(&g_commit, (double)t);
    }
}

__global__ void finalize_kernel(float* __restrict__ out_loss) {
    *out_loss = (float)(g_commit * (1.0 / ((double)NTOK * CBD)));
}

// ---------------- launch ---------------------------------------------------
extern "C" void kernel_launch(void* const* d_in, const int* in_sizes, int n_in,
                              void* d_out, int out_size) {
    const float* x  = (const float*)d_in[0];
    const float* W1 = (const float*)d_in[1];
    const float* b1 = (const float*)d_in[2];
    const float* W2 = (const float*)d_in[3];
    const float* b2 = (const float*)d_in[4];
    const float* cb = (const float*)d_in[5];
    const float* W3 = (const float*)d_in[6];
    const float* b3 = (const float*)d_in[7];
    const float* W4 = (const float*)d_in[8];
    const float* b4 = (const float*)d_in[9];

    float* out       = (float*)d_out;
    float* out_recon = out;
    float* out_idx   = out + (size_t)NTOK * D_IN;
    float* out_loss  = out_idx + NTOK;

    __half *phH, *phL, *pzH, *pzL;
    __half *pW1TH, *pW1TL, *pW2TH, *pW2TL, *pcbH, *pcbL;
    float *pT1, *pR;
    float2* ppart;
    cudaGetSymbolAddress((void**)&phH,   g_hH);
    cudaGetSymbolAddress((void**)&phL,   g_hL);
    cudaGetSymbolAddress((void**)&pzH,   g_zH);
    cudaGetSymbolAddress((void**)&pzL,   g_zL);
    cudaGetSymbolAddress((void**)&ppart, g_part);
    cudaGetSymbolAddress((void**)&pT1,   g_T1);
    cudaGetSymbolAddress((void**)&pR,    g_R);
    cudaGetSymbolAddress((void**)&pW1TH, g_W1TH);
    cudaGetSymbolAddress((void**)&pW1TL, g_W1TL);
    cudaGetSymbolAddress((void**)&pW2TH, g_W2TH);
    cudaGetSymbolAddress((void**)&pW2TL, g_W2TL);
    cudaGetSymbolAddress((void**)&pcbH,  g_cbH);
    cudaGetSymbolAddress((void**)&pcbL,  g_cbL);

    static bool attr_done = false;
    if (!attr_done) {
        cudaFuncSetAttribute(hmma_gemm<true,  true,  true,  false, true >,
                             cudaFuncAttributeMaxDynamicSharedMemorySize, HSMEM);
        cudaFuncSetAttribute(hmma_gemm<false, true,  true,  false, false>,
                             cudaFuncAttributeMaxDynamicSharedMemorySize, HSMEM);
        cudaFuncSetAttribute(hmma_gemm<false, false, false, true,  false>,
                             cudaFuncAttributeMaxDynamicSharedMemorySize, HSMEM);
        attr_done = true;
    }

    // [0] prep: cb split + csq + commit=0
    prep_kernel<<<514, 256>>>(cb);
    // [1][2] weight transpose+split
    transpose_split<<<(HID * D_IN + 255) / 256, 256>>>(W1, pW1TH, pW1TL, D_IN, HID);
    transpose_split<<<(CBD * HID + 255) / 256, 256>>>(W2, pW2TH, pW2TL, HID, CBD);
    // [3] h = relu(x @ W1 + b1), fp32 A converted in-kernel, split output
    hmma_gemm<true,  true,  true,  false, true ><<<dim3(HID / 128, NTOK / 128), 256, HSMEM>>>(
        x, nullptr, nullptr, pW1TH, pW1TL, b1, nullptr, phH, phL, nullptr, D_IN, HID);
    // [4][5] decoder table (tiny, fp32, 64x64 tiles)
    sgemm64<true , true ><<<dim3(HID  / 64, 512 / 64), 256>>>(cb,  W3, b3, pT1, 512, CBD, HID);
    sgemm64<false, true ><<<dim3(D_IN / 64, 512 / 64), 256>>>(pT1, W4, b4, pR,  512, HID, D_IN);
    // [6] z = h @ W2 + b2, split output
    hmma_gemm<false, true,  true,  false, false><<<dim3(CBD / 128, NTOK / 128), 256, HSMEM>>>(
        nullptr, phH, phL, pW2TH, pW2TL, b2, nullptr, pzH, pzL, nullptr, HID, CBD);
    // [7] dots + fused argmin -> partials
    hmma_gemm<false, false, false, true,  false><<<dim3(CBK / 128, NTOK / 128), 256, HSMEM>>>(
        nullptr, pzH, pzL, pcbH, pcbL, nullptr, nullptr, nullptr, nullptr, ppart, CBD, CBK);
    // [8] reduce partials + commit + recon gather
    vq_recon_kernel<<<NTOK / 64, 256>>>(ppart, pzH, pzL, pR, out_idx, out_recon);
    // [9] loss
    finalize_kernel<<<1, 1>>>(out_loss);
}

// round 13
// speedup vs baseline: 1.4076x; 1.0412x over previous
#include <cuda_runtime.h>
#include <cuda_fp16.h>
#include <cstdint>

#define NTOK 65536
#define D_IN 768
#define HID  512
#define CBD  256
#define CBK  512

// ---------------- scratch (device globals; no allocations) ----------------
__device__ __half g_hH[(size_t)NTOK * HID];
__device__ __half g_hL[(size_t)NTOK * HID];
__device__ __half g_zH[(size_t)NTOK * CBD];
__device__ __half g_zL[(size_t)NTOK * CBD];
__device__ float2 g_part[(size_t)NTOK * 4];   // per-128-code-block (val, idx)
__device__ __half g_W1TH[HID * D_IN];
__device__ __half g_W1TL[HID * D_IN];
__device__ __half g_W2TH[CBD * HID];
__device__ __half g_W2TL[CBD * HID];
__device__ __half g_cbH[CBK * CBD];
__device__ __half g_cbL[CBK * CBD];
__device__ float  g_T1[512 * 512];
__device__ float  g_R[512 * 768];
__device__ float  g_csq[CBK];
__device__ double g_commit;

// ---------------- helpers --------------------------------------------------
__device__ __forceinline__ void split_h(float v, __half& h, __half& l) {
    h = __float2half_rn(v);
    l = __float2half_rn(v - __half2float(h));
}
__device__ __forceinline__ void split8(float4 a, float4 b, uint4& H, uint4& L) {
    __half2 H2[4], L2[4];
    __half h0, l0, h1, l1;
    split_h(a.x, h0, l0); split_h(a.y, h1, l1);
    H2[0] = __halves2half2(h0, h1); L2[0] = __halves2half2(l0, l1);
    split_h(a.z, h0, l0); split_h(a.w, h1, l1);
    H2[1] = __halves2half2(h0, h1); L2[1] = __halves2half2(l0, l1);
    split_h(b.x, h0, l0); split_h(b.y, h1, l1);
    H2[2] = __halves2half2(h0, h1); L2[2] = __halves2half2(l0, l1);
    split_h(b.z, h0, l0); split_h(b.w, h1, l1);
    H2[3] = __halves2half2(h0, h1); L2[3] = __halves2half2(l0, l1);
    H = *(const uint4*)H2;
    L = *(const uint4*)L2;
}
__device__ __forceinline__ void cp16(uint32_t saddr, const void* g) {
    asm volatile("cp.async.cg.shared.global [%0], [%1], 16;" :: "r"(saddr), "l"(g));
}
#define CP_COMMIT() asm volatile("cp.async.commit_group;" ::: "memory")
#define CP_WAIT1()  asm volatile("cp.async.wait_group 1;" ::: "memory")

#define LDSM4(r0, r1, r2, r3, addr) \
    asm volatile("ldmatrix.sync.aligned.m8n8.x4.shared.b16 {%0,%1,%2,%3}, [%4];" \
        : "=r"(r0), "=r"(r1), "=r"(r2), "=r"(r3) : "r"(addr))

#define MMA16(cc, aa, bb) \
    asm volatile("mma.sync.aligned.m16n8k16.row.col.f32.f16.f16.f32 " \
        "{%0,%1,%2,%3}, {%4,%5,%6,%7}, {%8,%9}, {%0,%1,%2,%3};" \
        : "+f"((cc)[0]), "+f"((cc)[1]), "+f"((cc)[2]), "+f"((cc)[3]) \
        : "r"((aa)[0]), "r"((aa)[1]), "r"((aa)[2]), "r"((aa)[3]), \
          "r"((bb)[0]), "r"((bb)[1]))

// =================== fp16 3x-split HMMA GEMM ===============================
// C[N, M] = op((Ah+Al)[N,K] @ (Bh+Bl)^T + bias); planes are __half [.,K] rowmaj.
// CTA tile 128x128, 8 warps each 64x32, K-tile 32, 3-stage cp.async pipeline.
// Stage (32 KB): Ah@0, Al@8192, Bh@16384, Bl@24576. Row = 64B = 4 chunks of
// 16B; chunk c of row r stored at slot (c ^ ((r>>1)&3)) -> conflict-free LDSM.
// ACONV: A is fp32 (Af); loaded via register prefetch, split + STS in-kernel.
// ARGMIN: no C store; per-row argmin of (csq[col] - 2*acc) over the 128 cols.
#define STAGE_B  32768
#define HSMEM    (3 * STAGE_B)

template<bool RELU, bool HASBIAS, bool OSPLIT, bool ARGMIN, bool ACONV>
__global__ void __launch_bounds__(256, 2) hmma_gemm(
    const float* __restrict__ Af,
    const __half* __restrict__ Ah, const __half* __restrict__ Al,
    const __half* __restrict__ Bh, const __half* __restrict__ Bl,
    const float* __restrict__ bias,
    float* __restrict__ C, __half* __restrict__ Ch, __half* __restrict__ Cl,
    float2* __restrict__ part, int K, int M)
{
    extern __shared__ char hsm[];
    __shared__ float2 red[2][64][4];
    uint32_t sbase;
    asm("{ .reg .u64 t; cvta.to.shared.u64 t, %1; cvt.u32.u64 %0, t; }"
        : "=r"(sbase) : "l"(hsm));

    const int tid  = threadIdx.x;
    const int lane = tid & 31;
    const int wid  = tid >> 5;
    const int wm   = wid & 1;
    const int wn   = wid >> 1;
    const int group = lane >> 2;
    const int tig   = lane & 3;
    const int brow = blockIdx.y << 7;
    const int bcol = blockIdx.x << 7;

    // loader: thread -> (row = tid>>1, half = tid&1 -> chunks 2h, 2h+1)
    const int lrow = tid >> 1;
    const int lh   = tid & 1;
    const int c0   = lh << 1;
    const int lsw  = (lrow >> 1) & 3;
    const uint32_t off0 = (uint32_t)(lrow * 64 + (((c0)     ^ lsw) << 4));
    const uint32_t off1 = (uint32_t)(lrow * 64 + (((c0 | 1) ^ lsw) << 4));
    const __half* gAh = ACONV ? nullptr : (Ah + (size_t)(brow + lrow) * K + c0 * 8);
    const __half* gAl = ACONV ? nullptr : (Al + (size_t)(brow + lrow) * K + c0 * 8);
    const float*  gAf = ACONV ? (Af + (size_t)(brow + lrow) * K + lh * 16) : nullptr;
    const __half* gBh = Bh + (size_t)(bcol + lrow) * K + c0 * 8;
    const __half* gBl = Bl + (size_t)(bcol + lrow) * K + c0 * 8;

    // per-lane fragment address components
    const int laneHiA = lane >> 4;               // A chunk bit
    const int chBbit  = (lane >> 3) & 1;         // B chunk bit

    float c[4][4][4];
#pragma unroll
    for (int i = 0; i < 4; i++)
#pragma unroll
        for (int j = 0; j < 4; j++)
#pragma unroll
            for (int k = 0; k < 4; k++) c[i][j][k] = 0.f;

    const int KT = K >> 5;
    auto issue = [&](int kt, int stg) {
        const uint32_t sb = sbase + (uint32_t)stg * STAGE_B;
        const size_t go = (size_t)kt << 5;
        cp16(sb + 16384 + off0, gBh + go);
        cp16(sb + 16384 + off1, gBh + go + 8);
        cp16(sb + 24576 + off0, gBl + go);
        cp16(sb + 24576 + off1, gBl + go + 8);
        if (!ACONV) {
            cp16(sb +        off0, gAh + go);
            cp16(sb +        off1, gAh + go + 8);
            cp16(sb + 8192 + off0, gAl + go);
            cp16(sb + 8192 + off1, gAl + go + 8);
        }
    };

    float4 va[4];
    if (ACONV) {
        va[0] = *(const float4*)gAf;       va[1] = *(const float4*)(gAf + 4);
        va[2] = *(const float4*)(gAf + 8); va[3] = *(const float4*)(gAf + 12);
    }
    issue(0, 0); CP_COMMIT();
    issue(1, 1); CP_COMMIT();

    int st_c = 0;   // stage of tile kt
    int st_i = 2;   // stage of tile kt+2
    for (int kt = 0; kt < KT; kt++) {
        if (ACONV) {
            // split + STS A(kt) (chunks c0, c0+1), then prefetch A(kt+1)
            uint4 H, L;
            char* stp = hsm + (size_t)st_c * STAGE_B;
            split8(va[0], va[1], H, L);
            *(uint4*)(stp + off0)        = H;
            *(uint4*)(stp + 8192 + off0) = L;
            split8(va[2], va[3], H, L);
            *(uint4*)(stp + off1)        = H;
            *(uint4*)(stp + 8192 + off1) = L;
            if (kt + 1 < KT) {
                const float* p = gAf + (size_t)(kt + 1) * 32;
                va[0] = *(const float4*)p;        va[1] = *(const float4*)(p + 4);
                va[2] = *(const float4*)(p + 8);  va[3] = *(const float4*)(p + 12);
            }
        }
        CP_WAIT1();
        __syncthreads();
        if (kt + 2 < KT) issue(kt + 2, st_i);
        CP_COMMIT();

        const uint32_t st = sbase + (uint32_t)st_c * STAGE_B;

#pragma unroll
        for (int ks = 0; ks < 2; ks++) {
            // B fragments: pairs p=0 (nf0,1), p=1 (nf2,3), hi + lo planes
            uint32_t bh[4][2], bl[4][2];
#pragma unroll
            for (int p = 0; p < 2; p++) {
                const int colB = (wn << 5) + (p << 4) + (lane & 7) + ((lane >> 4) << 3);
                const int chB  = (ks << 1) + chBbit;
                const uint32_t ob = (uint32_t)(colB * 64 +
                                    (((chB ^ ((colB >> 1) & 3)) & 3) << 4));
                LDSM4(bh[2*p][0], bh[2*p][1], bh[2*p+1][0], bh[2*p+1][1],
                      st + 16384 + ob);
                LDSM4(bl[2*p][0], bl[2*p][1], bl[2*p+1][0], bl[2*p+1][1],
                      st + 24576 + ob);
            }
#pragma unroll
            for (int mf = 0; mf < 4; mf++) {
                const int rowA = (wm << 6) + (mf << 4) + (lane & 15);
                const int chA  = (ks << 1) + laneHiA;
                const uint32_t oa = (uint32_t)(rowA * 64 +
                                    (((chA ^ ((rowA >> 1) & 3)) & 3) << 4));
                uint32_t ah[4], al[4];
                LDSM4(ah[0], ah[1], ah[2], ah[3], st + oa);
                LDSM4(al[0], al[1], al[2], al[3], st + 8192 + oa);
#pragma unroll
                for (int nf = 0; nf < 4; nf++) MMA16(c[mf][nf], ah, bh[nf]);
#pragma unroll
                for (int nf = 0; nf < 4; nf++) MMA16(c[mf][nf], al, bh[nf]);
#pragma unroll
                for (int nf = 0; nf < 4; nf++) MMA16(c[mf][nf], ah, bl[nf]);
            }
        }
        st_c = (st_c == 2) ? 0 : st_c + 1;
        st_i = (st_i == 2) ? 0 : st_i + 1;
    }

    if (ARGMIN) {
#pragma unroll
        for (int mf = 0; mf < 4; mf++) {
#pragma unroll
            for (int sub = 0; sub < 2; sub++) {
                float bv = 3.4e38f;
                int   bi = 0;
#pragma unroll
                for (int nf = 0; nf < 4; nf++) {
                    const int col = (wn << 5) + (nf << 3) + (tig << 1);
                    float d0 = __ldg(&g_csq[bcol + col])     - 2.f * c[mf][nf][sub * 2];
                    float d1 = __ldg(&g_csq[bcol + col + 1]) - 2.f * c[mf][nf][sub * 2 + 1];
                    if (d0 < bv || (d0 == bv && col < bi))     { bv = d0; bi = col; }
                    if (d1 < bv || (d1 == bv && col + 1 < bi)) { bv = d1; bi = col + 1; }
                }
#pragma unroll
                for (int off = 1; off < 4; off <<= 1) {
                    float ov = __shfl_xor_sync(0xffffffffu, bv, off);
                    int   oi = __shfl_xor_sync(0xffffffffu, bi, off);
                    if (ov < bv || (ov == bv && oi < bi)) { bv = ov; bi = oi; }
                }
                if (tig == 0)
                    red[wm][(mf << 4) + group + sub * 8][wn] =
                        make_float2(bv, __int_as_float(bi));
            }
        }
        __syncthreads();
        if (tid < 128) {
            const int wmb = tid >> 6, rl = tid & 63;
            float bv = 3.4e38f;
            int   bi = 0;
#pragma unroll
            for (int w = 0; w < 4; w++) {
                float2 e = red[wmb][rl][w];
                int ei = __float_as_int(e.y);
                if (e.x < bv || (e.x == bv && ei < bi)) { bv = e.x; bi = ei; }
            }
            const int token = brow + (wmb << 6) + rl;
            part[(size_t)token * 4 + blockIdx.x] = make_float2(bv, (float)(bcol + bi));
        }
        return;
    }

    // normal epilogue
#pragma unroll
    for (int mf = 0; mf < 4; mf++) {
#pragma unroll
        for (int nf = 0; nf < 4; nf++) {
            const int row = brow + (wm << 6) + (mf << 4) + group;
            const int col = bcol + (wn << 5) + (nf << 3) + (tig << 1);
            float bx = 0.f, by = 0.f;
            if (HASBIAS) { bx = __ldg(bias + col); by = __ldg(bias + col + 1); }
            float2 o0, o1;
            o0.x = c[mf][nf][0] + bx;  o0.y = c[mf][nf][1] + by;
            o1.x = c[mf][nf][2] + bx;  o1.y = c[mf][nf][3] + by;
            if (RELU) {
                o0.x = fmaxf(o0.x, 0.f); o0.y = fmaxf(o0.y, 0.f);
                o1.x = fmaxf(o1.x, 0.f); o1.y = fmaxf(o1.y, 0.f);
            }
            if (OSPLIT) {
                __half hx, lx, hy, ly;
                split_h(o0.x, hx, lx); split_h(o0.y, hy, ly);
                *(__half2*)(Ch + (size_t)row * M + col) = __halves2half2(hx, hy);
                *(__half2*)(Cl + (size_t)row * M + col) = __halves2half2(lx, ly);
                split_h(o1.x, hx, lx); split_h(o1.y, hy, ly);
                *(__half2*)(Ch + (size_t)(row + 8) * M + col) = __halves2half2(hx, hy);
                *(__half2*)(Cl + (size_t)(row + 8) * M + col) = __halves2half2(lx, ly);
            } else {
                *(float2*)(C + (size_t)row * M + col)       = o0;
                *(float2*)(C + (size_t)(row + 8) * M + col) = o1;
            }
        }
    }
}

// ---------------- prep: cb split + csq + commit=0 --------------------------
__global__ void prep_kernel(const float* __restrict__ cb) {
    const int b = blockIdx.x;
    const int t = threadIdx.x;
    if (b < 512) {
        int idx = b * 256 + t;
        __half h, l;
        split_h(cb[idx], h, l);
        g_cbH[idx] = h;
        g_cbL[idx] = l;
    } else {
        int k = (b - 512) * 256 + t;
        if (b == 512 && t == 0) g_commit = 0.0;
        const float* row = cb + (size_t)k * CBD;
        float s = 0.f;
#pragma unroll 8
        for (int c = 0; c < CBD; c += 4) {
            float4 v = *(const float4*)(row + c);
            s += v.x*v.x + v.y*v.y + v.z*v.z + v.w*v.w;
        }
        g_csq[k] = s;
    }
}

// ---------------- transpose + split: W[K,M] -> half planes [M,K] -----------
__global__ void transpose_split(const float* __restrict__ W,
                                __half* __restrict__ WTh, __half* __restrict__ WTl,
                                int K, int M) {
    int idx = blockIdx.x * 256 + threadIdx.x;
    if (idx < K * M) {
        int m = idx / K, k = idx - m * K;
        __half h, l;
        split_h(W[(size_t)k * M + m], h, l);
        WTh[idx] = h;
        WTl[idx] = l;
    }
}

// -------- fp32 SGEMM 64x64 tiles for the tiny decoder-table GEMMs ---------
template<bool RELU, bool HASBIAS>
__global__ void __launch_bounds__(256) sgemm64(
    const float* __restrict__ A, const float* __restrict__ B,
    const float* __restrict__ bias, float* __restrict__ C,
    int N, int K, int M)
{
    __shared__ float As[16][68];
    __shared__ float Bs[16][68];
    const int tid  = threadIdx.x;
    const int tx   = tid & 15;
    const int ty   = tid >> 4;
    const int brow = blockIdx.y << 6;
    const int bcol = blockIdx.x << 6;

    const int ar = tid >> 2;
    const int ac = (tid & 3) << 2;
    const float* aptr = A + (size_t)(brow + ar) * K + ac;
    const int br = tid >> 4;
    const int bc = (tid & 15) << 2;
    const float* bptr = B + (size_t)br * M + bcol + bc;

    float acc[4][4];
#pragma unroll
    for (int i = 0; i < 4; i++)
#pragma unroll
        for (int j = 0; j < 4; j++) acc[i][j] = 0.f;

    for (int k0 = 0; k0 < K; k0 += 16) {
        float4 av = *(const float4*)(aptr + k0);
        float4 bv = *(const float4*)(bptr + (size_t)k0 * M);
        As[ac + 0][ar] = av.x;  As[ac + 1][ar] = av.y;
        As[ac + 2][ar] = av.z;  As[ac + 3][ar] = av.w;
        *(float4*)&Bs[br][bc] = bv;
        __syncthreads();
#pragma unroll
        for (int kk = 0; kk < 16; kk++) {
            float4 a4 = *(const float4*)&As[kk][ty << 2];
            float4 b4 = *(const float4*)&Bs[kk][tx << 2];
            float arr[4] = {a4.x, a4.y, a4.z, a4.w};
            float brr[4] = {b4.x, b4.y, b4.z, b4.w};
#pragma unroll
            for (int i = 0; i < 4; i++)
#pragma unroll
                for (int j = 0; j < 4; j++)
                    acc[i][j] = fmaf(arr[i], brr[j], acc[i][j]);
        }
        __syncthreads();
    }

    float4 bb = make_float4(0.f, 0.f, 0.f, 0.f);
    if (HASBIAS) bb = *(const float4*)(bias + bcol + (tx << 2));
#pragma unroll
    for (int i = 0; i < 4; i++) {
        float4 o;
        o.x = acc[i][0] + bb.x;
        o.y = acc[i][1] + bb.y;
        o.z = acc[i][2] + bb.z;
        o.w = acc[i][3] + bb.w;
        if (RELU) {
            o.x = fmaxf(o.x, 0.f); o.y = fmaxf(o.y, 0.f);
            o.z = fmaxf(o.z, 0.f); o.w = fmaxf(o.w, 0.f);
        }
        *(float4*)(C + (size_t)(brow + (ty << 2) + i) * M + bcol + (tx << 2)) = o;
    }
}

// ---- VQ: reduce 4 partials + commit partial + recon gather ---------------
__global__ void __launch_bounds__(256) vq_recon_kernel(
    const float2* __restrict__ part,
    const __half* __restrict__ zH, const __half* __restrict__ zL,
    const float* __restrict__ R, float* __restrict__ out_idx,
    float* __restrict__ out_recon)
{
    __shared__ float s_part[8];
    const int tid = threadIdx.x;
    const int token = (blockIdx.x << 6) + (tid >> 2);
    const int lpart = tid & 3;

    float2 e = part[(size_t)token * 4 + lpart];
    float best = e.x;
    int   bidx = (int)e.y;
#pragma unroll
    for (int off = 1; off < 4; off <<= 1) {
        float ob = __shfl_xor_sync(0xffffffffu, best, off);
        int   oi = __shfl_xor_sync(0xffffffffu, bidx, off);
        if (ob < best || (ob == best && oi < bidx)) { best = ob; bidx = oi; }
    }

    // ||z||^2 from half planes (z = zH + zL); 64 coords per lane
    const __half2* zh2 = (const __half2*)(zH + (size_t)token * CBD + (lpart << 6));
    const __half2* zl2 = (const __half2*)(zL + (size_t)token * CBD + (lpart << 6));
    float s = 0.f;
#pragma unroll
    for (int i = 0; i < 32; i++) {
        float2 a = __half22float2(zh2[i]);
        float2 b = __half22float2(zl2[i]);
        float vx = a.x + b.x, vy = a.y + b.y;
        s += vx * vx + vy * vy;
    }
    s += __shfl_xor_sync(0xffffffffu, s, 1);
    s += __shfl_xor_sync(0xffffffffu, s, 2);

    float cv = (lpart == 0) ? (s + best) : 0.f;
    if (lpart == 0) out_idx[token] = (float)bidx;

    const float4* src = (const float4*)(R + (size_t)bidx * D_IN + lpart * 192);
    float4*       dst = (float4*)(out_recon + (size_t)token * D_IN + lpart * 192);
#pragma unroll 4
    for (int i = 0; i < 48; i++) dst[i] = src[i];

#pragma unroll
    for (int off = 16; off; off >>= 1) cv += __shfl_xor_sync(0xffffffffu, cv, off);
    if ((tid & 31) == 0) s_part[tid >> 5] = cv;
    __syncthreads();
    if (tid == 0) {
        float t = 0.f;
#pragma unroll
        for (int w = 0; w < 8; w++) t += s_part[w];
        atomicAdd(&g_commit, (double)t);
    }
}

__global__ void finalize_kernel(float* __restrict__ out_loss) {
    *out_loss = (float)(g_commit * (1.0 / ((double)NTOK * CBD)));
}

// ---------------- launch ---------------------------------------------------
extern "C" void kernel_launch(void* const* d_in, const int* in_sizes, int n_in,
                              void* d_out, int out_size) {
    const float* x  = (const float*)d_in[0];
    const float* W1 = (const float*)d_in[1];
    const float* b1 = (const float*)d_in[2];
    const float* W2 = (const float*)d_in[3];
    const float* b2 = (const float*)d_in[4];
    const float* cb = (const float*)d_in[5];
    const float* W3 = (const float*)d_in[6];
    const float* b3 = (const float*)d_in[7];
    const float* W4 = (const float*)d_in[8];
    const float* b4 = (const float*)d_in[9];

    float* out       = (float*)d_out;
    float* out_recon = out;
    float* out_idx   = out + (size_t)NTOK * D_IN;
    float* out_loss  = out_idx + NTOK;

    __half *phH, *phL, *pzH, *pzL;
    __half *pW1TH, *pW1TL, *pW2TH, *pW2TL, *pcbH, *pcbL;
    float *pT1, *pR;
    float2* ppart;
    cudaGetSymbolAddress((void**)&phH,   g_hH);
    cudaGetSymbolAddress((void**)&phL,   g_hL);
    cudaGetSymbolAddress((void**)&pzH,   g_zH);
    cudaGetSymbolAddress((void**)&pzL,   g_zL);
    cudaGetSymbolAddress((void**)&ppart, g_part);
    cudaGetSymbolAddress((void**)&pT1,   g_T1);
    cudaGetSymbolAddress((void**)&pR,    g_R);
    cudaGetSymbolAddress((void**)&pW1TH, g_W1TH);
    cudaGetSymbolAddress((void**)&pW1TL, g_W1TL);
    cudaGetSymbolAddress((void**)&pW2TH, g_W2TH);
    cudaGetSymbolAddress((void**)&pW2TL, g_W2TL);
    cudaGetSymbolAddress((void**)&pcbH,  g_cbH);
    cudaGetSymbolAddress((void**)&pcbL,  g_cbL);

    static bool attr_done = false;
    if (!attr_done) {
        cudaFuncSetAttribute(hmma_gemm<true,  true,  true,  false, true >,
                             cudaFuncAttributeMaxDynamicSharedMemorySize, HSMEM);
        cudaFuncSetAttribute(hmma_gemm<false, true,  true,  false, false>,
                             cudaFuncAttributeMaxDynamicSharedMemorySize, HSMEM);
        cudaFuncSetAttribute(hmma_gemm<false, false, false, true,  false>,
                             cudaFuncAttributeMaxDynamicSharedMemorySize, HSMEM);
        attr_done = true;
    }

    // [0] prep: cb split + csq + commit=0
    prep_kernel<<<514, 256>>>(cb);
    // [1][2] weight transpose+split
    transpose_split<<<(HID * D_IN + 255) / 256, 256>>>(W1, pW1TH, pW1TL, D_IN, HID);
    transpose_split<<<(CBD * HID + 255) / 256, 256>>>(W2, pW2TH, pW2TL, HID, CBD);
    // [3] h = relu(x @ W1 + b1), fp32 A converted in-kernel, split output
    hmma_gemm<true,  true,  true,  false, true ><<<dim3(HID / 128, NTOK / 128), 256, HSMEM>>>(
        x, nullptr, nullptr, pW1TH, pW1TL, b1, nullptr, phH, phL, nullptr, D_IN, HID);
    // [4][5] decoder table (tiny, fp32, 64x64 tiles)
    sgemm64<true , true ><<<dim3(HID  / 64, 512 / 64), 256>>>(cb,  W3, b3, pT1, 512, CBD, HID);
    sgemm64<false, true ><<<dim3(D_IN / 64, 512 / 64), 256>>>(pT1, W4, b4, pR,  512, HID, D_IN);
    // [6] z = h @ W2 + b2, split output
    hmma_gemm<false, true,  true,  false, false><<<dim3(CBD / 128, NTOK / 128), 256, HSMEM>>>(
        nullptr, phH, phL, pW2TH, pW2TL, b2, nullptr, pzH, pzL, nullptr, HID, CBD);
    // [7] dots + fused argmin -> partials
    hmma_gemm<false, false, false, true,  false><<<dim3(CBK / 128, NTOK / 128), 256, HSMEM>>>(
        nullptr, pzH, pzL, pcbH, pcbL, nullptr, nullptr, nullptr, nullptr, ppart, CBD, CBK);
    // [8] reduce partials + commit + recon gather
    vq_recon_kernel<<<NTOK / 64, 256>>>(ppart, pzH, pzL, pR, out_idx, out_recon);
    // [9] loss
    finalize_kernel<<<1, 1>>>(out_loss);
}

// round 14
// speedup vs baseline: 1.5077x; 1.0711x over previous
#include <cuda_runtime.h>
#include <cuda_fp16.h>
#include <cstdint>

#define NTOK 65536
#define D_IN 768
#define HID  512
#define CBD  256
#define CBK  512

// ---------------- scratch (device globals; no allocations) ----------------
__device__ __half g_hH[(size_t)NTOK * HID];
__device__ __half g_hL[(size_t)NTOK * HID];
__device__ __half g_zH[(size_t)NTOK * CBD];
__device__ __half g_zL[(size_t)NTOK * CBD];
__device__ float  g_zsqp[(size_t)NTOK * 2];   // per-col-block ||z||^2 partials
__device__ float2 g_part[(size_t)NTOK * 4];   // per-128-code-block (val, idx)
__device__ __half g_W1TH[HID * D_IN];
__device__ __half g_W1TL[HID * D_IN];
__device__ __half g_W2TH[CBD * HID];
__device__ __half g_W2TL[CBD * HID];
__device__ __half g_cbH[CBK * CBD];
__device__ __half g_cbL[CBK * CBD];
__device__ float  g_T1[512 * 512];
__device__ float  g_R[512 * 768];
__device__ float  g_csq[CBK];
__device__ double g_commit;

// ---------------- helpers --------------------------------------------------
__device__ __forceinline__ void split_h(float v, __half& h, __half& l) {
    h = __float2half_rn(v);
    l = __float2half_rn(v - __half2float(h));
}
__device__ __forceinline__ void split8(float4 a, float4 b, uint4& H, uint4& L) {
    __half2 H2[4], L2[4];
    __half h0, l0, h1, l1;
    split_h(a.x, h0, l0); split_h(a.y, h1, l1);
    H2[0] = __halves2half2(h0, h1); L2[0] = __halves2half2(l0, l1);
    split_h(a.z, h0, l0); split_h(a.w, h1, l1);
    H2[1] = __halves2half2(h0, h1); L2[1] = __halves2half2(l0, l1);
    split_h(b.x, h0, l0); split_h(b.y, h1, l1);
    H2[2] = __halves2half2(h0, h1); L2[2] = __halves2half2(l0, l1);
    split_h(b.z, h0, l0); split_h(b.w, h1, l1);
    H2[3] = __halves2half2(h0, h1); L2[3] = __halves2half2(l0, l1);
    H = *(const uint4*)H2;
    L = *(const uint4*)L2;
}
__device__ __forceinline__ void cp16(uint32_t saddr, const void* g) {
    asm volatile("cp.async.cg.shared.global [%0], [%1], 16;" :: "r"(saddr), "l"(g));
}
#define CP_COMMIT() asm volatile("cp.async.commit_group;" ::: "memory")
#define CP_WAIT1()  asm volatile("cp.async.wait_group 1;" ::: "memory")

#define LDSM4(r0, r1, r2, r3, addr) \
    asm volatile("ldmatrix.sync.aligned.m8n8.x4.shared.b16 {%0,%1,%2,%3}, [%4];" \
        : "=r"(r0), "=r"(r1), "=r"(r2), "=r"(r3) : "r"(addr))

#define MMA16(cc, aa, bb) \
    asm volatile("mma.sync.aligned.m16n8k16.row.col.f32.f16.f16.f32 " \
        "{%0,%1,%2,%3}, {%4,%5,%6,%7}, {%8,%9}, {%0,%1,%2,%3};" \
        : "+f"((cc)[0]), "+f"((cc)[1]), "+f"((cc)[2]), "+f"((cc)[3]) \
        : "r"((aa)[0]), "r"((aa)[1]), "r"((aa)[2]), "r"((aa)[3]), \
          "r"((bb)[0]), "r"((bb)[1]))

// =================== fp16 3x-split HMMA GEMM ===============================
// C[N, M] = op((Ah+Al)[N,K] @ (Bh+Bl)^T + bias); planes are __half [.,K] rowmaj.
// CTA tile 128x128, 8 warps each 64x32, K-tile 32, 3-stage cp.async pipeline.
// Stage (32 KB): Ah@0, Al@8192, Bh@16384, Bl@24576. Row = 64B = 4 chunks of
// 16B; chunk c of row r stored at slot (c ^ ((r>>1)&3)) -> conflict-free LDSM.
// ACONV: A is fp32 (Af); loaded via register prefetch, split + STS in-kernel.
// ARGMIN: no C store; per-row argmin of (csq[col] - 2*acc) over the 128 cols.
// ZSQ (with OSPLIT): also reduce per-row sum of C^2 -> zsqp[row*2 + blockIdx.x].
#define STAGE_B  32768
#define HSMEM    (3 * STAGE_B)

template<bool RELU, bool HASBIAS, bool OSPLIT, bool ARGMIN, bool ACONV, bool ZSQ>
__global__ void __launch_bounds__(256, 2) hmma_gemm(
    const float* __restrict__ Af,
    const __half* __restrict__ Ah, const __half* __restrict__ Al,
    const __half* __restrict__ Bh, const __half* __restrict__ Bl,
    const float* __restrict__ bias,
    float* __restrict__ C, __half* __restrict__ Ch, __half* __restrict__ Cl,
    float2* __restrict__ part, float* __restrict__ zsqp, int K, int M)
{
    extern __shared__ char hsm[];
    __shared__ float2 red[2][64][4];
    uint32_t sbase;
    asm("{ .reg .u64 t; cvta.to.shared.u64 t, %1; cvt.u32.u64 %0, t; }"
        : "=r"(sbase) : "l"(hsm));

    const int tid  = threadIdx.x;
    const int lane = tid & 31;
    const int wid  = tid >> 5;
    const int wm   = wid & 1;
    const int wn   = wid >> 1;
    const int group = lane >> 2;
    const int tig   = lane & 3;
    const int brow = blockIdx.y << 7;
    const int bcol = blockIdx.x << 7;

    // loader: thread -> (row = tid>>1, half = tid&1 -> chunks 2h, 2h+1)
    const int lrow = tid >> 1;
    const int lh   = tid & 1;
    const int c0   = lh << 1;
    const int lsw  = (lrow >> 1) & 3;
    const uint32_t off0 = (uint32_t)(lrow * 64 + (((c0)     ^ lsw) << 4));
    const uint32_t off1 = (uint32_t)(lrow * 64 + (((c0 | 1) ^ lsw) << 4));
    const __half* gAh = ACONV ? nullptr : (Ah + (size_t)(brow + lrow) * K + c0 * 8);
    const __half* gAl = ACONV ? nullptr : (Al + (size_t)(brow + lrow) * K + c0 * 8);
    const float*  gAf = ACONV ? (Af + (size_t)(brow + lrow) * K + lh * 16) : nullptr;
    const __half* gBh = Bh + (size_t)(bcol + lrow) * K + c0 * 8;
    const __half* gBl = Bl + (size_t)(bcol + lrow) * K + c0 * 8;

    // per-lane fragment address components
    const int laneHiA = lane >> 4;               // A chunk bit
    const int chBbit  = (lane >> 3) & 1;         // B chunk bit

    float c[4][4][4];
#pragma unroll
    for (int i = 0; i < 4; i++)
#pragma unroll
        for (int j = 0; j < 4; j++)
#pragma unroll
            for (int k = 0; k < 4; k++) c[i][j][k] = 0.f;

    const int KT = K >> 5;
    auto issue = [&](int kt, int stg) {
        const uint32_t sb = sbase + (uint32_t)stg * STAGE_B;
        const size_t go = (size_t)kt << 5;
        cp16(sb + 16384 + off0, gBh + go);
        cp16(sb + 16384 + off1, gBh + go + 8);
        cp16(sb + 24576 + off0, gBl + go);
        cp16(sb + 24576 + off1, gBl + go + 8);
        if (!ACONV) {
            cp16(sb +        off0, gAh + go);
            cp16(sb +        off1, gAh + go + 8);
            cp16(sb + 8192 + off0, gAl + go);
            cp16(sb + 8192 + off1, gAl + go + 8);
        }
    };

    float4 va[4];
    if (ACONV) {
        va[0] = *(const float4*)gAf;       va[1] = *(const float4*)(gAf + 4);
        va[2] = *(const float4*)(gAf + 8); va[3] = *(const float4*)(gAf + 12);
    }
    issue(0, 0); CP_COMMIT();
    issue(1, 1); CP_COMMIT();

    int st_c = 0;   // stage of tile kt
    int st_i = 2;   // stage of tile kt+2
    for (int kt = 0; kt < KT; kt++) {
        if (ACONV) {
            // split + STS A(kt) (chunks c0, c0+1), then prefetch A(kt+1)
            uint4 H, L;
            char* stp = hsm + (size_t)st_c * STAGE_B;
            split8(va[0], va[1], H, L);
            *(uint4*)(stp + off0)        = H;
            *(uint4*)(stp + 8192 + off0) = L;
            split8(va[2], va[3], H, L);
            *(uint4*)(stp + off1)        = H;
            *(uint4*)(stp + 8192 + off1) = L;
            if (kt + 1 < KT) {
                const float* p = gAf + (size_t)(kt + 1) * 32;
                va[0] = *(const float4*)p;        va[1] = *(const float4*)(p + 4);
                va[2] = *(const float4*)(p + 8);  va[3] = *(const float4*)(p + 12);
            }
        }
        CP_WAIT1();
        __syncthreads();
        if (kt + 2 < KT) issue(kt + 2, st_i);
        CP_COMMIT();

        const uint32_t st = sbase + (uint32_t)st_c * STAGE_B;

#pragma unroll
        for (int ks = 0; ks < 2; ks++) {
            // B fragments: pairs p=0 (nf0,1), p=1 (nf2,3), hi + lo planes
            uint32_t bh[4][2], bl[4][2];
#pragma unroll
            for (int p = 0; p < 2; p++) {
                const int colB = (wn << 5) + (p << 4) + (lane & 7) + ((lane >> 4) << 3);
                const int chB  = (ks << 1) + chBbit;
                const uint32_t ob = (uint32_t)(colB * 64 +
                                    (((chB ^ ((colB >> 1) & 3)) & 3) << 4));
                LDSM4(bh[2*p][0], bh[2*p][1], bh[2*p+1][0], bh[2*p+1][1],
                      st + 16384 + ob);
                LDSM4(bl[2*p][0], bl[2*p][1], bl[2*p+1][0], bl[2*p+1][1],
                      st + 24576 + ob);
            }
#pragma unroll
            for (int mf = 0; mf < 4; mf++) {
                const int rowA = (wm << 6) + (mf << 4) + (lane & 15);
                const int chA  = (ks << 1) + laneHiA;
                const uint32_t oa = (uint32_t)(rowA * 64 +
                                    (((chA ^ ((rowA >> 1) & 3)) & 3) << 4));
                uint32_t ah[4], al[4];
                LDSM4(ah[0], ah[1], ah[2], ah[3], st + oa);
                LDSM4(al[0], al[1], al[2], al[3], st + 8192 + oa);
#pragma unroll
                for (int nf = 0; nf < 4; nf++) MMA16(c[mf][nf], ah, bh[nf]);
#pragma unroll
                for (int nf = 0; nf < 4; nf++) MMA16(c[mf][nf], al, bh[nf]);
#pragma unroll
                for (int nf = 0; nf < 4; nf++) MMA16(c[mf][nf], ah, bl[nf]);
            }
        }
        st_c = (st_c == 2) ? 0 : st_c + 1;
        st_i = (st_i == 2) ? 0 : st_i + 1;
    }

    if (ARGMIN) {
#pragma unroll
        for (int mf = 0; mf < 4; mf++) {
#pragma unroll
            for (int sub = 0; sub < 2; sub++) {
                float bv = 3.4e38f;
                int   bi = 0;
#pragma unroll
                for (int nf = 0; nf < 4; nf++) {
                    const int col = (wn << 5) + (nf << 3) + (tig << 1);
                    float d0 = __ldg(&g_csq[bcol + col])     - 2.f * c[mf][nf][sub * 2];
                    float d1 = __ldg(&g_csq[bcol + col + 1]) - 2.f * c[mf][nf][sub * 2 + 1];
                    if (d0 < bv || (d0 == bv && col < bi))     { bv = d0; bi = col; }
                    if (d1 < bv || (d1 == bv && col + 1 < bi)) { bv = d1; bi = col + 1; }
                }
#pragma unroll
                for (int off = 1; off < 4; off <<= 1) {
                    float ov = __shfl_xor_sync(0xffffffffu, bv, off);
                    int   oi = __shfl_xor_sync(0xffffffffu, bi, off);
                    if (ov < bv || (ov == bv && oi < bi)) { bv = ov; bi = oi; }
                }
                if (tig == 0)
                    red[wm][(mf << 4) + group + sub * 8][wn] =
                        make_float2(bv, __int_as_float(bi));
            }
        }
        __syncthreads();
        if (tid < 128) {
            const int wmb = tid >> 6, rl = tid & 63;
            float bv = 3.4e38f;
            int   bi = 0;
#pragma unroll
            for (int w = 0; w < 4; w++) {
                float2 e = red[wmb][rl][w];
                int ei = __float_as_int(e.y);
                if (e.x < bv || (e.x == bv && ei < bi)) { bv = e.x; bi = ei; }
            }
            const int token = brow + (wmb << 6) + rl;
            part[(size_t)token * 4 + blockIdx.x] = make_float2(bv, (float)(bcol + bi));
        }
        return;
    }

    // normal epilogue (optionally with fused ||row||^2 partial reduction)
#pragma unroll
    for (int mf = 0; mf < 4; mf++) {
        float rs0 = 0.f, rs1 = 0.f;
#pragma unroll
        for (int nf = 0; nf < 4; nf++) {
            const int row = brow + (wm << 6) + (mf << 4) + group;
            const int col = bcol + (wn << 5) + (nf << 3) + (tig << 1);
            float bx = 0.f, by = 0.f;
            if (HASBIAS) { bx = __ldg(bias + col); by = __ldg(bias + col + 1); }
            float2 o0, o1;
            o0.x = c[mf][nf][0] + bx;  o0.y = c[mf][nf][1] + by;
            o1.x = c[mf][nf][2] + bx;  o1.y = c[mf][nf][3] + by;
            if (RELU) {
                o0.x = fmaxf(o0.x, 0.f); o0.y = fmaxf(o0.y, 0.f);
                o1.x = fmaxf(o1.x, 0.f); o1.y = fmaxf(o1.y, 0.f);
            }
            if (ZSQ) {
                rs0 += o0.x * o0.x + o0.y * o0.y;
                rs1 += o1.x * o1.x + o1.y * o1.y;
            }
            if (OSPLIT) {
                __half hx, lx, hy, ly;
                split_h(o0.x, hx, lx); split_h(o0.y, hy, ly);
                *(__half2*)(Ch + (size_t)row * M + col) = __halves2half2(hx, hy);
                *(__half2*)(Cl + (size_t)row * M + col) = __halves2half2(lx, ly);
                split_h(o1.x, hx, lx); split_h(o1.y, hy, ly);
                *(__half2*)(Ch + (size_t)(row + 8) * M + col) = __halves2half2(hx, hy);
                *(__half2*)(Cl + (size_t)(row + 8) * M + col) = __halves2half2(lx, ly);
            } else {
                *(float2*)(C + (size_t)row * M + col)       = o0;
                *(float2*)(C + (size_t)(row + 8) * M + col) = o1;
            }
        }
        if (ZSQ) {
            rs0 += __shfl_xor_sync(0xffffffffu, rs0, 1);
            rs0 += __shfl_xor_sync(0xffffffffu, rs0, 2);
            rs1 += __shfl_xor_sync(0xffffffffu, rs1, 1);
            rs1 += __shfl_xor_sync(0xffffffffu, rs1, 2);
            if (tig == 0) {
                red[wm][(mf << 4) + group][wn].x     = rs0;
                red[wm][(mf << 4) + group + 8][wn].x = rs1;
            }
        }
    }
    if (ZSQ) {
        __syncthreads();
        if (tid < 128) {
            const int wmb = tid >> 6, rl = tid & 63;
            float s = red[wmb][rl][0].x + red[wmb][rl][1].x +
                      red[wmb][rl][2].x + red[wmb][rl][3].x;
            const int token = brow + (wmb << 6) + rl;
            zsqp[(size_t)token * 2 + blockIdx.x] = s;
        }
    }
}

// ---------------- merged prep: cb split + csq + W1/W2 transpose-split ------
__global__ void prep_all(const float* __restrict__ cb,
                         const float* __restrict__ W1,
                         const float* __restrict__ W2) {
    const int b = blockIdx.x;
    const int t = threadIdx.x;
    if (b < 512) {
        int idx = b * 256 + t;
        __half h, l;
        split_h(cb[idx], h, l);
        g_cbH[idx] = h;
        g_cbL[idx] = l;
    } else if (b < 514) {
        int k = (b - 512) * 256 + t;
        if (b == 512 && t == 0) g_commit = 0.0;
        const float* row = cb + (size_t)k * CBD;
        float s = 0.f;
#pragma unroll 8
        for (int c = 0; c < CBD; c += 4) {
            float4 v = *(const float4*)(row + c);
            s += v.x*v.x + v.y*v.y + v.z*v.z + v.w*v.w;
        }
        g_csq[k] = s;
    } else if (b < 514 + 1536) {
        // W1 [768,512] -> planes [512,768]
        int idx = (b - 514) * 256 + t;
        int m = idx / D_IN, k = idx - m * D_IN;
        __half h, l;
        split_h(W1[(size_t)k * HID + m], h, l);
        g_W1TH[idx] = h;
        g_W1TL[idx] = l;
    } else {
        // W2 [512,256] -> planes [256,512]
        int idx = (b - 2050) * 256 + t;
        int m = idx / HID, k = idx - m * HID;
        __half h, l;
        split_h(W2[(size_t)k * CBD + m], h, l);
        g_W2TH[idx] = h;
        g_W2TL[idx] = l;
    }
}

// -------- fp32 SGEMM 64x64 tiles for the tiny decoder-table GEMMs ---------
template<bool RELU, bool HASBIAS>
__global__ void __launch_bounds__(256) sgemm64(
    const float* __restrict__ A, const float* __restrict__ B,
    const float* __restrict__ bias, float* __restrict__ C,
    int N, int K, int M)
{
    __shared__ float As[16][68];
    __shared__ float Bs[16][68];
    const int tid  = threadIdx.x;
    const int tx   = tid & 15;
    const int ty   = tid >> 4;
    const int brow = blockIdx.y << 6;
    const int bcol = blockIdx.x << 6;

    const int ar = tid >> 2;
    const int ac = (tid & 3) << 2;
    const float* aptr = A + (size_t)(brow + ar) * K + ac;
    const int br = tid >> 4;
    const int bc = (tid & 15) << 2;
    const float* bptr = B + (size_t)br * M + bcol + bc;

    float acc[4][4];
#pragma unroll
    for (int i = 0; i < 4; i++)
#pragma unroll
        for (int j = 0; j < 4; j++) acc[i][j] = 0.f;

    for (int k0 = 0; k0 < K; k0 += 16) {
        float4 av = *(const float4*)(aptr + k0);
        float4 bv = *(const float4*)(bptr + (size_t)k0 * M);
        As[ac + 0][ar] = av.x;  As[ac + 1][ar] = av.y;
        As[ac + 2][ar] = av.z;  As[ac + 3][ar] = av.w;
        *(float4*)&Bs[br][bc] = bv;
        __syncthreads();
#pragma unroll
        for (int kk = 0; kk < 16; kk++) {
            float4 a4 = *(const float4*)&As[kk][ty << 2];
            float4 b4 = *(const float4*)&Bs[kk][tx << 2];
            float arr[4] = {a4.x, a4.y, a4.z, a4.w};
            float brr[4] = {b4.x, b4.y, b4.z, b4.w};
#pragma unroll
            for (int i = 0; i < 4; i++)
#pragma unroll
                for (int j = 0; j < 4; j++)
                    acc[i][j] = fmaf(arr[i], brr[j], acc[i][j]);
        }
        __syncthreads();
    }

    float4 bb = make_float4(0.f, 0.f, 0.f, 0.f);
    if (HASBIAS) bb = *(const float4*)(bias + bcol + (tx << 2));
#pragma unroll
    for (int i = 0; i < 4; i++) {
        float4 o;
        o.x = acc[i][0] + bb.x;
        o.y = acc[i][1] + bb.y;
        o.z = acc[i][2] + bb.z;
        o.w = acc[i][3] + bb.w;
        if (RELU) {
            o.x = fmaxf(o.x, 0.f); o.y = fmaxf(o.y, 0.f);
            o.z = fmaxf(o.z, 0.f); o.w = fmaxf(o.w, 0.f);
        }
        *(float4*)(C + (size_t)(brow + (ty << 2) + i) * M + bcol + (tx << 2)) = o;
    }
}

// ---- VQ: reduce 4 partials + commit partial + recon gather ---------------
__global__ void __launch_bounds__(256) vq_recon_kernel(
    const float2* __restrict__ part, const float* __restrict__ zsqp,
    const float* __restrict__ R, float* __restrict__ out_idx,
    float* __restrict__ out_recon)
{
    __shared__ float s_part[8];
    const int tid = threadIdx.x;
    const int token = (blockIdx.x << 6) + (tid >> 2);
    const int lpart = tid & 3;

    float2 e = part[(size_t)token * 4 + lpart];
    float best = e.x;
    int   bidx = (int)e.y;
#pragma unroll
    for (int off = 1; off < 4; off <<= 1) {
        float ob = __shfl_xor_sync(0xffffffffu, best, off);
        int   oi = __shfl_xor_sync(0xffffffffu, bidx, off);
        if (ob < best || (ob == best && oi < bidx)) { best = ob; bidx = oi; }
    }

    float cv = 0.f;
    if (lpart == 0) {
        float zsq = zsqp[(size_t)token * 2] + zsqp[(size_t)token * 2 + 1];
        cv = zsq + best;
        out_idx[token] = (float)bidx;
    }

    const float4* src = (const float4*)(R + (size_t)bidx * D_IN + lpart * 192);
    float4*       dst = (float4*)(out_recon + (size_t)token * D_IN + lpart * 192);
#pragma unroll 4
    for (int i = 0; i < 48; i++) dst[i] = src[i];

#pragma unroll
    for (int off = 16; off; off >>= 1) cv += __shfl_xor_sync(0xffffffffu, cv, off);
    if ((tid & 31) == 0) s_part[tid >> 5] = cv;
    __syncthreads();
    if (tid == 0) {
        float t = 0.f;
#pragma unroll
        for (int w = 0; w < 8; w++) t += s_part[w];
        atomicAdd(&g_commit, (double)t);
    }
}

__global__ void finalize_kernel(float* __restrict__ out_loss) {
    *out_loss = (float)(g_commit * (1.0 / ((double)NTOK * CBD)));
}

// ---------------- launch ---------------------------------------------------
extern "C" void kernel_launch(void* const* d_in, const int* in_sizes, int n_in,
                              void* d_out, int out_size) {
    const float* x  = (const float*)d_in[0];
    const float* W1 = (const float*)d_in[1];
    const float* b1 = (const float*)d_in[2];
    const float* W2 = (const float*)d_in[3];
    const float* b2 = (const float*)d_in[4];
    const float* cb = (const float*)d_in[5];
    const float* W3 = (const float*)d_in[6];
    const float* b3 = (const float*)d_in[7];
    const float* W4 = (const float*)d_in[8];
    const float* b4 = (const float*)d_in[9];

    float* out       = (float*)d_out;
    float* out_recon = out;
    float* out_idx   = out + (size_t)NTOK * D_IN;
    float* out_loss  = out_idx + NTOK;

    __half *phH, *phL, *pzH, *pzL;
    __half *pW1TH, *pW1TL, *pW2TH, *pW2TL, *pcbH, *pcbL;
    float *pT1, *pR, *pzsqp;
    float2* ppart;
    cudaGetSymbolAddress((void**)&phH,   g_hH);
    cudaGetSymbolAddress((void**)&phL,   g_hL);
    cudaGetSymbolAddress((void**)&pzH,   g_zH);
    cudaGetSymbolAddress((void**)&pzL,   g_zL);
    cudaGetSymbolAddress((void**)&pzsqp, g_zsqp);
    cudaGetSymbolAddress((void**)&ppart, g_part);
    cudaGetSymbolAddress((void**)&pT1,   g_T1);
    cudaGetSymbolAddress((void**)&pR,    g_R);
    cudaGetSymbolAddress((void**)&pW1TH, g_W1TH);
    cudaGetSymbolAddress((void**)&pW1TL, g_W1TL);
    cudaGetSymbolAddress((void**)&pW2TH, g_W2TH);
    cudaGetSymbolAddress((void**)&pW2TL, g_W2TL);
    cudaGetSymbolAddress((void**)&pcbH,  g_cbH);
    cudaGetSymbolAddress((void**)&pcbL,  g_cbL);

    static bool attr_done = false;
    if (!attr_done) {
        cudaFuncSetAttribute(hmma_gemm<true,  true,  true,  false, true,  false>,
                             cudaFuncAttributeMaxDynamicSharedMemorySize, HSMEM);
        cudaFuncSetAttribute(hmma_gemm<false, true,  true,  false, false, true >,
                             cudaFuncAttributeMaxDynamicSharedMemorySize, HSMEM);
        cudaFuncSetAttribute(hmma_gemm<false, false, false, true,  false, false>,
                             cudaFuncAttributeMaxDynamicSharedMemorySize, HSMEM);
        attr_done = true;
    }

    // [0] merged prep: cb split + csq + commit=0 + W1/W2 transpose-split
    prep_all<<<2562, 256>>>(cb, W1, W2);
    // [1] h = relu(x @ W1 + b1), fp32 A converted in-kernel, split output
    hmma_gemm<true,  true,  true,  false, true,  false><<<dim3(HID / 128, NTOK / 128), 256, HSMEM>>>(
        x, nullptr, nullptr, pW1TH, pW1TL, b1, nullptr, phH, phL, nullptr, nullptr, D_IN, HID);
    // [2][3] decoder table (tiny, fp32, 64x64 tiles)
    sgemm64<true , true ><<<dim3(HID  / 64, 512 / 64), 256>>>(cb,  W3, b3, pT1, 512, CBD, HID);
    sgemm64<false, true ><<<dim3(D_IN / 64, 512 / 64), 256>>>(pT1, W4, b4, pR,  512, HID, D_IN);
    // [4] z = h @ W2 + b2, split output + fused ||z||^2 partials
    hmma_gemm<false, true,  true,  false, false, true ><<<dim3(CBD / 128, NTOK / 128), 256, HSMEM>>>(
        nullptr, phH, phL, pW2TH, pW2TL, b2, nullptr, pzH, pzL, nullptr, pzsqp, HID, CBD);
    // [5] dots + fused argmin -> partials
    hmma_gemm<false, false, false, true,  false, false><<<dim3(CBK / 128, NTOK / 128), 256, HSMEM>>>(
        nullptr, pzH, pzL, pcbH, pcbL, nullptr, nullptr, nullptr, nullptr, ppart, nullptr, CBD, CBK);
    // [6] reduce partials + commit + recon gather
    vq_recon_kernel<<<NTOK / 64, 256>>>(ppart, pzsqp, pR, out_idx, out_recon);
    // [7] loss
    finalize_kernel<<<1, 1>>>(out_loss);
}

// round 15
// speedup vs baseline: 1.7052x; 1.1310x over previous
#include <cuda_runtime.h>
#include <cuda_fp16.h>
#include <cstdint>

#define NTOK 65536
#define D_IN 768
#define HID  512
#define CBD  256
#define CBK  512

// ---------------- scratch (device globals; no allocations) ----------------
__device__ __half g_hH[(size_t)NTOK * HID];
__device__ __half g_hL[(size_t)NTOK * HID];
__device__ __half g_zH[(size_t)NTOK * CBD];
__device__ __half g_zL[(size_t)NTOK * CBD];
__device__ float  g_zsqp[(size_t)NTOK * 2];   // per-col-block ||z||^2 partials
__device__ __half g_W1TH[HID * D_IN];
__device__ __half g_W1TL[HID * D_IN];
__device__ __half g_W2TH[CBD * HID];
__device__ __half g_W2TL[CBD * HID];
__device__ __half g_cbH[CBK * CBD];
__device__ __half g_cbL[CBK * CBD];
__device__ float  g_T1[512 * 512];
__device__ float  g_R[512 * 768];
__device__ float  g_csq[CBK];
__device__ double g_commit;

// ---------------- helpers --------------------------------------------------
__device__ __forceinline__ void split_h(float v, __half& h, __half& l) {
    h = __float2half_rn(v);
    l = __float2half_rn(v - __half2float(h));
}
__device__ __forceinline__ void split8(float4 a, float4 b, uint4& H, uint4& L) {
    __half2 H2[4], L2[4];
    __half h0, l0, h1, l1;
    split_h(a.x, h0, l0); split_h(a.y, h1, l1);
    H2[0] = __halves2half2(h0, h1); L2[0] = __halves2half2(l0, l1);
    split_h(a.z, h0, l0); split_h(a.w, h1, l1);
    H2[1] = __halves2half2(h0, h1); L2[1] = __halves2half2(l0, l1);
    split_h(b.x, h0, l0); split_h(b.y, h1, l1);
    H2[2] = __halves2half2(h0, h1); L2[2] = __halves2half2(l0, l1);
    split_h(b.z, h0, l0); split_h(b.w, h1, l1);
    H2[3] = __halves2half2(h0, h1); L2[3] = __halves2half2(l0, l1);
    H = *(const uint4*)H2;
    L = *(const uint4*)L2;
}
__device__ __forceinline__ void cp16(uint32_t saddr, const void* g) {
    asm volatile("cp.async.cg.shared.global [%0], [%1], 16;" :: "r"(saddr), "l"(g));
}
#define CP_COMMIT() asm volatile("cp.async.commit_group;" ::: "memory")
#define CP_WAIT1()  asm volatile("cp.async.wait_group 1;" ::: "memory")

#define LDSM4(r0, r1, r2, r3, addr) \
    asm volatile("ldmatrix.sync.aligned.m8n8.x4.shared.b16 {%0,%1,%2,%3}, [%4];" \
        : "=r"(r0), "=r"(r1), "=r"(r2), "=r"(r3) : "r"(addr))

#define MMA16(cc, aa, bb) \
    asm volatile("mma.sync.aligned.m16n8k16.row.col.f32.f16.f16.f32 " \
        "{%0,%1,%2,%3}, {%4,%5,%6,%7}, {%8,%9}, {%0,%1,%2,%3};" \
        : "+f"((cc)[0]), "+f"((cc)[1]), "+f"((cc)[2]), "+f"((cc)[3]) \
        : "r"((aa)[0]), "r"((aa)[1]), "r"((aa)[2]), "r"((aa)[3]), \
          "r"((bb)[0]), "r"((bb)[1]))

#define STAGE_B  32768
#define HSMEM    (3 * STAGE_B)

// =================== fp16 3x-split HMMA GEMM ===============================
// C[N, M] = op((Ah+Al)[N,K] @ (Bh+Bl)^T + bias); planes are __half [.,K] rowmaj.
// CTA tile 128x128, 8 warps each 64x32, K-tile 32, 3-stage cp.async pipeline.
// Stage (32 KB): Ah@0, Al@8192, Bh@16384, Bl@24576. Row = 64B = 4 chunks of
// 16B; chunk c of row r stored at slot (c ^ ((r>>1)&3)) -> conflict-free LDSM.
// ACONV: A is fp32 (Af); loaded via register prefetch, split + STS in-kernel.
// ZSQ: also reduce per-row sum of C^2 -> zsqp[row*2 + blockIdx.x].
template<bool RELU, bool HASBIAS, bool OSPLIT, bool ACONV, bool ZSQ>
__global__ void __launch_bounds__(256, 2) hmma_gemm(
    const float* __restrict__ Af,
    const __half* __restrict__ Ah, const __half* __restrict__ Al,
    const __half* __restrict__ Bh, const __half* __restrict__ Bl,
    const float* __restrict__ bias,
    float* __restrict__ C, __half* __restrict__ Ch, __half* __restrict__ Cl,
    float* __restrict__ zsqp, int K, int M)
{
    extern __shared__ char hsm[];
    __shared__ float red[2][64][4];
    uint32_t sbase;
    asm("{ .reg .u64 t; cvta.to.shared.u64 t, %1; cvt.u32.u64 %0, t; }"
        : "=r"(sbase) : "l"(hsm));

    const int tid  = threadIdx.x;
    const int lane = tid & 31;
    const int wid  = tid >> 5;
    const int wm   = wid & 1;
    const int wn   = wid >> 1;
    const int group = lane >> 2;
    const int tig   = lane & 3;
    const int brow = blockIdx.y << 7;
    const int bcol = blockIdx.x << 7;

    const int lrow = tid >> 1;
    const int lh   = tid & 1;
    const int c0   = lh << 1;
    const int lsw  = (lrow >> 1) & 3;
    const uint32_t off0 = (uint32_t)(lrow * 64 + (((c0)     ^ lsw) << 4));
    const uint32_t off1 = (uint32_t)(lrow * 64 + (((c0 | 1) ^ lsw) << 4));
    const __half* gAh = ACONV ? nullptr : (Ah + (size_t)(brow + lrow) * K + c0 * 8);
    const __half* gAl = ACONV ? nullptr : (Al + (size_t)(brow + lrow) * K + c0 * 8);
    const float*  gAf = ACONV ? (Af + (size_t)(brow + lrow) * K + lh * 16) : nullptr;
    const __half* gBh = Bh + (size_t)(bcol + lrow) * K + c0 * 8;
    const __half* gBl = Bl + (size_t)(bcol + lrow) * K + c0 * 8;

    const int laneHiA = lane >> 4;
    const int chBbit  = (lane >> 3) & 1;

    float c[4][4][4];
#pragma unroll
    for (int i = 0; i < 4; i++)
#pragma unroll
        for (int j = 0; j < 4; j++)
#pragma unroll
            for (int k = 0; k < 4; k++) c[i][j][k] = 0.f;

    const int KT = K >> 5;
    auto issue = [&](int kt, int stg) {
        const uint32_t sb = sbase + (uint32_t)stg * STAGE_B;
        const size_t go = (size_t)kt << 5;
        cp16(sb + 16384 + off0, gBh + go);
        cp16(sb + 16384 + off1, gBh + go + 8);
        cp16(sb + 24576 + off0, gBl + go);
        cp16(sb + 24576 + off1, gBl + go + 8);
        if (!ACONV) {
            cp16(sb +        off0, gAh + go);
            cp16(sb +        off1, gAh + go + 8);
            cp16(sb + 8192 + off0, gAl + go);
            cp16(sb + 8192 + off1, gAl + go + 8);
        }
    };

    float4 va[4];
    if (ACONV) {
        va[0] = *(const float4*)gAf;       va[1] = *(const float4*)(gAf + 4);
        va[2] = *(const float4*)(gAf + 8); va[3] = *(const float4*)(gAf + 12);
    }
    issue(0, 0); CP_COMMIT();
    issue(1, 1); CP_COMMIT();

    int st_c = 0, st_i = 2;
    for (int kt = 0; kt < KT; kt++) {
        if (ACONV) {
            uint4 H, L;
            char* stp = hsm + (size_t)st_c * STAGE_B;
            split8(va[0], va[1], H, L);
            *(uint4*)(stp + off0)        = H;
            *(uint4*)(stp + 8192 + off0) = L;
            split8(va[2], va[3], H, L);
            *(uint4*)(stp + off1)        = H;
            *(uint4*)(stp + 8192 + off1) = L;
            if (kt + 1 < KT) {
                const float* p = gAf + (size_t)(kt + 1) * 32;
                va[0] = *(const float4*)p;        va[1] = *(const float4*)(p + 4);
                va[2] = *(const float4*)(p + 8);  va[3] = *(const float4*)(p + 12);
            }
        }
        CP_WAIT1();
        __syncthreads();
        if (kt + 2 < KT) issue(kt + 2, st_i);
        CP_COMMIT();

        const uint32_t st = sbase + (uint32_t)st_c * STAGE_B;
#pragma unroll
        for (int ks = 0; ks < 2; ks++) {
            uint32_t bh[4][2], bl[4][2];
#pragma unroll
            for (int p = 0; p < 2; p++) {
                const int colB = (wn << 5) + (p << 4) + (lane & 7) + ((lane >> 4) << 3);
                const int chB  = (ks << 1) + chBbit;
                const uint32_t ob = (uint32_t)(colB * 64 +
                                    (((chB ^ ((colB >> 1) & 3)) & 3) << 4));
                LDSM4(bh[2*p][0], bh[2*p][1], bh[2*p+1][0], bh[2*p+1][1],
                      st + 16384 + ob);
                LDSM4(bl[2*p][0], bl[2*p][1], bl[2*p+1][0], bl[2*p+1][1],
                      st + 24576 + ob);
            }
#pragma unroll
            for (int mf = 0; mf < 4; mf++) {
                const int rowA = (wm << 6) + (mf << 4) + (lane & 15);
                const int chA  = (ks << 1) + laneHiA;
                const uint32_t oa = (uint32_t)(rowA * 64 +
                                    (((chA ^ ((rowA >> 1) & 3)) & 3) << 4));
                uint32_t ah[4], al[4];
                LDSM4(ah[0], ah[1], ah[2], ah[3], st + oa);
                LDSM4(al[0], al[1], al[2], al[3], st + 8192 + oa);
#pragma unroll
                for (int nf = 0; nf < 4; nf++) MMA16(c[mf][nf], ah, bh[nf]);
#pragma unroll
                for (int nf = 0; nf < 4; nf++) MMA16(c[mf][nf], al, bh[nf]);
#pragma unroll
                for (int nf = 0; nf < 4; nf++) MMA16(c[mf][nf], ah, bl[nf]);
            }
        }
        st_c = (st_c == 2) ? 0 : st_c + 1;
        st_i = (st_i == 2) ? 0 : st_i + 1;
    }

    // epilogue (optionally with fused ||row||^2 partial reduction)
#pragma unroll
    for (int mf = 0; mf < 4; mf++) {
        float rs0 = 0.f, rs1 = 0.f;
#pragma unroll
        for (int nf = 0; nf < 4; nf++) {
            const int row = brow + (wm << 6) + (mf << 4) + group;
            const int col = bcol + (wn << 5) + (nf << 3) + (tig << 1);
            float bx = 0.f, by = 0.f;
            if (HASBIAS) { bx = __ldg(bias + col); by = __ldg(bias + col + 1); }
            float2 o0, o1;
            o0.x = c[mf][nf][0] + bx;  o0.y = c[mf][nf][1] + by;
            o1.x = c[mf][nf][2] + bx;  o1.y = c[mf][nf][3] + by;
            if (RELU) {
                o0.x = fmaxf(o0.x, 0.f); o0.y = fmaxf(o0.y, 0.f);
                o1.x = fmaxf(o1.x, 0.f); o1.y = fmaxf(o1.y, 0.f);
            }
            if (ZSQ) {
                rs0 += o0.x * o0.x + o0.y * o0.y;
                rs1 += o1.x * o1.x + o1.y * o1.y;
            }
            if (OSPLIT) {
                __half hx, lx, hy, ly;
                split_h(o0.x, hx, lx); split_h(o0.y, hy, ly);
                *(__half2*)(Ch + (size_t)row * M + col) = __halves2half2(hx, hy);
                *(__half2*)(Cl + (size_t)row * M + col) = __halves2half2(lx, ly);
                split_h(o1.x, hx, lx); split_h(o1.y, hy, ly);
                *(__half2*)(Ch + (size_t)(row + 8) * M + col) = __halves2half2(hx, hy);
                *(__half2*)(Cl + (size_t)(row + 8) * M + col) = __halves2half2(lx, ly);
            } else {
                *(float2*)(C + (size_t)row * M + col)       = o0;
                *(float2*)(C + (size_t)(row + 8) * M + col) = o1;
            }
        }
        if (ZSQ) {
            rs0 += __shfl_xor_sync(0xffffffffu, rs0, 1);
            rs0 += __shfl_xor_sync(0xffffffffu, rs0, 2);
            rs1 += __shfl_xor_sync(0xffffffffu, rs1, 1);
            rs1 += __shfl_xor_sync(0xffffffffu, rs1, 2);
            if (tig == 0) {
                red[wm][(mf << 4) + group][wn]     = rs0;
                red[wm][(mf << 4) + group + 8][wn] = rs1;
            }
        }
    }
    if (ZSQ) {
        __syncthreads();
        if (tid < 128) {
            const int wmb = tid >> 6, rl = tid & 63;
            float s = red[wmb][rl][0] + red[wmb][rl][1] +
                      red[wmb][rl][2] + red[wmb][rl][3];
            zsqp[(size_t)(brow + tid) * 2 + blockIdx.x] = s;
        }
    }
}

// ============== dots + argmin over all 512 codes + recon gather ============
// One CTA per 128-token block. 32 virtual k-tiles (4 code blocks x KT=8),
// cp.async ring uninterrupted across blocks. Running argmin kept in smem.
// Epilogue: out_idx, commit partial, recon gather from R.
__global__ void __launch_bounds__(256, 2) dots_argmin_kernel(
    const __half* __restrict__ zH, const __half* __restrict__ zL,
    const __half* __restrict__ cbH, const __half* __restrict__ cbL,
    const float* __restrict__ zsqp, const float* __restrict__ R,
    float* __restrict__ out_idx, float* __restrict__ out_recon)
{
    extern __shared__ char hsm[];
    __shared__ float2 red[2][64][4];
    __shared__ int   s_idx[128];
    __shared__ float s_sum[4];
    uint32_t sbase;
    asm("{ .reg .u64 t; cvta.to.shared.u64 t, %1; cvt.u32.u64 %0, t; }"
        : "=r"(sbase) : "l"(hsm));

    const int tid  = threadIdx.x;
    const int lane = tid & 31;
    const int wid  = tid >> 5;
    const int wm   = wid & 1;
    const int wn   = wid >> 1;
    const int group = lane >> 2;
    const int tig   = lane & 3;
    const int brow = blockIdx.x << 7;
    const int K = CBD;   // 256

    const int lrow = tid >> 1;
    const int lh   = tid & 1;
    const int c0   = lh << 1;
    const int lsw  = (lrow >> 1) & 3;
    const uint32_t off0 = (uint32_t)(lrow * 64 + (((c0)     ^ lsw) << 4));
    const uint32_t off1 = (uint32_t)(lrow * 64 + (((c0 | 1) ^ lsw) << 4));
    const __half* gAh = zH + (size_t)(brow + lrow) * K + c0 * 8;
    const __half* gAl = zL + (size_t)(brow + lrow) * K + c0 * 8;
    const __half* gBh = cbH + (size_t)lrow * K + c0 * 8;
    const __half* gBl = cbL + (size_t)lrow * K + c0 * 8;

    const int laneHiA = lane >> 4;
    const int chBbit  = (lane >> 3) & 1;

    // init running-argmin smem
    for (int i = tid; i < 512; i += 256)
        ((float2*)red)[i] = make_float2(3.4e38f, __int_as_float(0));

    float c[4][4][4];
#pragma unroll
    for (int i = 0; i < 4; i++)
#pragma unroll
        for (int j = 0; j < 4; j++)
#pragma unroll
            for (int k = 0; k < 4; k++) c[i][j][k] = 0.f;

    auto issue = [&](int vt, int stg) {
        const uint32_t sb = sbase + (uint32_t)stg * STAGE_B;
        const size_t goA = (size_t)(vt & 7) << 5;
        const size_t goB = ((size_t)(vt >> 3) << 7) * K + goA;
        cp16(sb +        off0, gAh + goA);
        cp16(sb +        off1, gAh + goA + 8);
        cp16(sb + 8192 + off0, gAl + goA);
        cp16(sb + 8192 + off1, gAl + goA + 8);
        cp16(sb + 16384 + off0, gBh + goB);
        cp16(sb + 16384 + off1, gBh + goB + 8);
        cp16(sb + 24576 + off0, gBl + goB);
        cp16(sb + 24576 + off1, gBl + goB + 8);
    };

    issue(0, 0); CP_COMMIT();
    issue(1, 1); CP_COMMIT();

    int st_c = 0, st_i = 2;
    for (int vt = 0; vt < 32; vt++) {
        CP_WAIT1();
        __syncthreads();
        if (vt + 2 < 32) issue(vt + 2, st_i);
        CP_COMMIT();

        const uint32_t st = sbase + (uint32_t)st_c * STAGE_B;
#pragma unroll
        for (int ks = 0; ks < 2; ks++) {
            uint32_t bh[4][2], bl[4][2];
#pragma unroll
            for (int p = 0; p < 2; p++) {
                const int colB = (wn << 5) + (p << 4) + (lane & 7) + ((lane >> 4) << 3);
                const int chB  = (ks << 1) + chBbit;
                const uint32_t ob = (uint32_t)(colB * 64 +
                                    (((chB ^ ((colB >> 1) & 3)) & 3) << 4));
                LDSM4(bh[2*p][0], bh[2*p][1], bh[2*p+1][0], bh[2*p+1][1],
                      st + 16384 + ob);
                LDSM4(bl[2*p][0], bl[2*p][1], bl[2*p+1][0], bl[2*p+1][1],
                      st + 24576 + ob);
            }
#pragma unroll
            for (int mf = 0; mf < 4; mf++) {
                const int rowA = (wm << 6) + (mf << 4) + (lane & 15);
                const int chA  = (ks << 1) + laneHiA;
                const uint32_t oa = (uint32_t)(rowA * 64 +
                                    (((chA ^ ((rowA >> 1) & 3)) & 3) << 4));
                uint32_t ah[4], al[4];
                LDSM4(ah[0], ah[1], ah[2], ah[3], st + oa);
                LDSM4(al[0], al[1], al[2], al[3], st + 8192 + oa);
#pragma unroll
                for (int nf = 0; nf < 4; nf++) MMA16(c[mf][nf], ah, bh[nf]);
#pragma unroll
                for (int nf = 0; nf < 4; nf++) MMA16(c[mf][nf], al, bh[nf]);
#pragma unroll
                for (int nf = 0; nf < 4; nf++) MMA16(c[mf][nf], ah, bl[nf]);
            }
        }
        st_c = (st_c == 2) ? 0 : st_c + 1;
        st_i = (st_i == 2) ? 0 : st_i + 1;

        if ((vt & 7) == 7) {
            const int colbase = (vt >> 3) << 7;
#pragma unroll
            for (int mf = 0; mf < 4; mf++) {
#pragma unroll
                for (int sub = 0; sub < 2; sub++) {
                    float bv = 3.4e38f;
                    int   bi = 0;
#pragma unroll
                    for (int nf = 0; nf < 4; nf++) {
                        const int col = (wn << 5) + (nf << 3) + (tig << 1);
                        float d0 = __ldg(&g_csq[colbase + col])     - 2.f * c[mf][nf][sub * 2];
                        float d1 = __ldg(&g_csq[colbase + col + 1]) - 2.f * c[mf][nf][sub * 2 + 1];
                        if (d0 < bv || (d0 == bv && col < bi))     { bv = d0; bi = col; }
                        if (d1 < bv || (d1 == bv && col + 1 < bi)) { bv = d1; bi = col + 1; }
                    }
#pragma unroll
                    for (int off = 1; off < 4; off <<= 1) {
                        float ov = __shfl_xor_sync(0xffffffffu, bv, off);
                        int   oi = __shfl_xor_sync(0xffffffffu, bi, off);
                        if (ov < bv || (ov == bv && oi < bi)) { bv = ov; bi = oi; }
                    }
                    if (tig == 0) {
                        float2* slot = &red[wm][(mf << 4) + group + sub * 8][wn];
                        float2 cur = *slot;
                        const int gbi = colbase + bi;
                        if (bv < cur.x ||
                            (bv == cur.x && gbi < __float_as_int(cur.y)))
                            *slot = make_float2(bv, __int_as_float(gbi));
                    }
                }
            }
#pragma unroll
            for (int i = 0; i < 4; i++)
#pragma unroll
                for (int j = 0; j < 4; j++)
#pragma unroll
                    for (int k = 0; k < 4; k++) c[i][j][k] = 0.f;
        }
    }

    __syncthreads();
    if (tid < 128) {
        const int token = brow + tid;
        float bv = 3.4e38f;
        int   bi = 0;
#pragma unroll
        for (int w = 0; w < 4; w++) {
            float2 e = red[tid >> 6][tid & 63][w];
            int ei = __float_as_int(e.y);
            if (e.x < bv || (e.x == bv && ei < bi)) { bv = e.x; bi = ei; }
        }
        out_idx[token] = (float)bi;
        s_idx[tid] = bi;
        float cv = zsqp[(size_t)token * 2] + zsqp[(size_t)token * 2 + 1] + bv;
#pragma unroll
        for (int off = 16; off; off >>= 1) cv += __shfl_xor_sync(0xffffffffu, cv, off);
        if ((tid & 31) == 0) s_sum[tid >> 5] = cv;
    }
    __syncthreads();
    if (tid == 0)
        atomicAdd(&g_commit, (double)(s_sum[0] + s_sum[1] + s_sum[2] + s_sum[3]));

    // recon gather: 128 tokens x 192 float4
    for (int i = tid; i < 128 * 192; i += 256) {
        const int tok = i / 192;
        const int j   = i - tok * 192;
        ((float4*)(out_recon + (size_t)(brow + tok) * D_IN))[j] =
            ((const float4*)(R + (size_t)s_idx[tok] * D_IN))[j];
    }
}

// ---------------- merged prep: cb split + csq + W1/W2 transpose-split ------
__global__ void prep_all(const float* __restrict__ cb,
                         const float* __restrict__ W1,
                         const float* __restrict__ W2) {
    const int b = blockIdx.x;
    const int t = threadIdx.x;
    if (b < 512) {
        int idx = b * 256 + t;
        __half h, l;
        split_h(cb[idx], h, l);
        g_cbH[idx] = h;
        g_cbL[idx] = l;
    } else if (b < 514) {
        int k = (b - 512) * 256 + t;
        if (b == 512 && t == 0) g_commit = 0.0;
        const float* row = cb + (size_t)k * CBD;
        float s = 0.f;
#pragma unroll 8
        for (int c = 0; c < CBD; c += 4) {
            float4 v = *(const float4*)(row + c);
            s += v.x*v.x + v.y*v.y + v.z*v.z + v.w*v.w;
        }
        g_csq[k] = s;
    } else if (b < 514 + 1536) {
        int idx = (b - 514) * 256 + t;
        int m = idx / D_IN, k = idx - m * D_IN;
        __half h, l;
        split_h(W1[(size_t)k * HID + m], h, l);
        g_W1TH[idx] = h;
        g_W1TL[idx] = l;
    } else {
        int idx = (b - 2050) * 256 + t;
        int m = idx / HID, k = idx - m * HID;
        __half h, l;
        split_h(W2[(size_t)k * CBD + m], h, l);
        g_W2TH[idx] = h;
        g_W2TL[idx] = l;
    }
}

// -------- fp32 SGEMM 64x64 tiles for the tiny decoder-table GEMMs ---------
template<bool RELU, bool HASBIAS>
__global__ void __launch_bounds__(256) sgemm64(
    const float* __restrict__ A, const float* __restrict__ B,
    const float* __restrict__ bias, float* __restrict__ C,
    int N, int K, int M)
{
    __shared__ float As[16][68];
    __shared__ float Bs[16][68];
    const int tid  = threadIdx.x;
    const int tx   = tid & 15;
    const int ty   = tid >> 4;
    const int brow = blockIdx.y << 6;
    const int bcol = blockIdx.x << 6;

    const int ar = tid >> 2;
    const int ac = (tid & 3) << 2;
    const float* aptr = A + (size_t)(brow + ar) * K + ac;
    const int br = tid >> 4;
    const int bc = (tid & 15) << 2;
    const float* bptr = B + (size_t)br * M + bcol + bc;

    float acc[4][4];
#pragma unroll
    for (int i = 0; i < 4; i++)
#pragma unroll
        for (int j = 0; j < 4; j++) acc[i][j] = 0.f;

    for (int k0 = 0; k0 < K; k0 += 16) {
        float4 av = *(const float4*)(aptr + k0);
        float4 bv = *(const float4*)(bptr + (size_t)k0 * M);
        As[ac + 0][ar] = av.x;  As[ac + 1][ar] = av.y;
        As[ac + 2][ar] = av.z;  As[ac + 3][ar] = av.w;
        *(float4*)&Bs[br][bc] = bv;
        __syncthreads();
#pragma unroll
        for (int kk = 0; kk < 16; kk++) {
            float4 a4 = *(const float4*)&As[kk][ty << 2];
            float4 b4 = *(const float4*)&Bs[kk][tx << 2];
            float arr[4] = {a4.x, a4.y, a4.z, a4.w};
            float brr[4] = {b4.x, b4.y, b4.z, b4.w};
#pragma unroll
            for (int i = 0; i < 4; i++)
#pragma unroll
                for (int j = 0; j < 4; j++)
                    acc[i][j] = fmaf(arr[i], brr[j], acc[i][j]);
        }
        __syncthreads();
    }

    float4 bb = make_float4(0.f, 0.f, 0.f, 0.f);
    if (HASBIAS) bb = *(const float4*)(bias + bcol + (tx << 2));
#pragma unroll
    for (int i = 0; i < 4; i++) {
        float4 o;
        o.x = acc[i][0] + bb.x;
        o.y = acc[i][1] + bb.y;
        o.z = acc[i][2] + bb.z;
        o.w = acc[i][3] + bb.w;
        if (RELU) {
            o.x = fmaxf(o.x, 0.f); o.y = fmaxf(o.y, 0.f);
            o.z = fmaxf(o.z, 0.f); o.w = fmaxf(o.w, 0.f);
        }
        *(float4*)(C + (size_t)(brow + (ty << 2) + i) * M + bcol + (tx << 2)) = o;
    }
}

__global__ void finalize_kernel(float* __restrict__ out_loss) {
    *out_loss = (float)(g_commit * (1.0 / ((double)NTOK * CBD)));
}

// ---------------- launch ---------------------------------------------------
extern "C" void kernel_launch(void* const* d_in, const int* in_sizes, int n_in,
                              void* d_out, int out_size) {
    const float* x  = (const float*)d_in[0];
    const float* W1 = (const float*)d_in[1];
    const float* b1 = (const float*)d_in[2];
    const float* W2 = (const float*)d_in[3];
    const float* b2 = (const float*)d_in[4];
    const float* cb = (const float*)d_in[5];
    const float* W3 = (const float*)d_in[6];
    const float* b3 = (const float*)d_in[7];
    const float* W4 = (const float*)d_in[8];
    const float* b4 = (const float*)d_in[9];

    float* out       = (float*)d_out;
    float* out_recon = out;
    float* out_idx   = out + (size_t)NTOK * D_IN;
    float* out_loss  = out_idx + NTOK;

    __half *phH, *phL, *pzH, *pzL;
    __half *pW1TH, *pW1TL, *pW2TH, *pW2TL, *pcbH, *pcbL;
    float *pT1, *pR, *pzsqp;
    cudaGetSymbolAddress((void**)&phH,   g_hH);
    cudaGetSymbolAddress((void**)&phL,   g_hL);
    cudaGetSymbolAddress((void**)&pzH,   g_zH);
    cudaGetSymbolAddress((void**)&pzL,   g_zL);
    cudaGetSymbolAddress((void**)&pzsqp, g_zsqp);
    cudaGetSymbolAddress((void**)&pT1,   g_T1);
    cudaGetSymbolAddress((void**)&pR,    g_R);
    cudaGetSymbolAddress((void**)&pW1TH, g_W1TH);
    cudaGetSymbolAddress((void**)&pW1TL, g_W1TL);
    cudaGetSymbolAddress((void**)&pW2TH, g_W2TH);
    cudaGetSymbolAddress((void**)&pW2TL, g_W2TL);
    cudaGetSymbolAddress((void**)&pcbH,  g_cbH);
    cudaGetSymbolAddress((void**)&pcbL,  g_cbL);

    static cudaStream_t s1 = nullptr;
    static cudaEvent_t ev0, ev1;
    static bool init_done = false;
    if (!init_done) {
        cudaFuncSetAttribute(hmma_gemm<true,  true,  true,  true,  false>,
                             cudaFuncAttributeMaxDynamicSharedMemorySize, HSMEM);
        cudaFuncSetAttribute(hmma_gemm<false, true,  true,  false, true >,
                             cudaFuncAttributeMaxDynamicSharedMemorySize, HSMEM);
        cudaFuncSetAttribute(dots_argmin_kernel,
                             cudaFuncAttributeMaxDynamicSharedMemorySize, HSMEM);
        cudaStreamCreateWithFlags(&s1, cudaStreamNonBlocking);
        cudaEventCreateWithFlags(&ev0, cudaEventDisableTiming);
        cudaEventCreateWithFlags(&ev1, cudaEventDisableTiming);
        init_done = true;
    }

    // fork: decoder table (depends only on cb/W3/W4) runs on side stream
    cudaEventRecord(ev0, 0);
    cudaStreamWaitEvent(s1, ev0, 0);
    sgemm64<true , true ><<<dim3(HID  / 64, 512 / 64), 256, 0, s1>>>(cb,  W3, b3, pT1, 512, CBD, HID);
    sgemm64<false, true ><<<dim3(D_IN / 64, 512 / 64), 256, 0, s1>>>(pT1, W4, b4, pR,  512, HID, D_IN);
    cudaEventRecord(ev1, s1);

    // main chain
    prep_all<<<2562, 256>>>(cb, W1, W2);
    hmma_gemm<true,  true,  true,  true,  false><<<dim3(HID / 128, NTOK / 128), 256, HSMEM>>>(
        x, nullptr, nullptr, pW1TH, pW1TL, b1, nullptr, phH, phL, nullptr, D_IN, HID);
    hmma_gemm<false, true,  true,  false, true ><<<dim3(CBD / 128, NTOK / 128), 256, HSMEM>>>(
        nullptr, phH, phL, pW2TH, pW2TL, b2, nullptr, pzH, pzL, pzsqp, HID, CBD);

    // join: dots/recon needs R
    cudaStreamWaitEvent(0, ev1, 0);
    dots_argmin_kernel<<<NTOK / 128, 256, HSMEM>>>(
        pzH, pzL, pcbH, pcbL, pzsqp, pR, out_idx, out_recon);
    finalize_kernel<<<1, 1>>>(out_loss);
}